// round 1
// baseline (speedup 1.0000x reference)
#include <cuda_runtime.h>
#include <cstdint>

#define BB 16
#define NN 4096
#define MM 1024
#define K0 32
#define K1 64
#define P0 (BB*MM*K0)   // 524288
#define P1 (BB*MM*K1)   // 1048576
#define OUT_OFS (BB*3*MM) // 49152

// ---------------- scratch (device globals; no allocation allowed) ----------------
__device__ int   g_samp[BB*MM];
__device__ int   g_idx0[BB*MM*K0];
__device__ int   g_idx1[BB*MM*K1];
__device__ float g_bufA[134217728];   // 128 * P1 floats (512 MB)
__device__ float g_bufB[100663296];   //  96 * P1 floats (384 MB)
__device__ float g_s[128];
__device__ float g_t[128];

// ---------------- FPS: one block per batch, coords+dmin in registers ----------------
__global__ __launch_bounds__(512) void fps_kernel(const float* __restrict__ pc,
                                                  int* __restrict__ samp,
                                                  float* __restrict__ dout)
{
    int b   = blockIdx.x;
    int tid = threadIdx.x;
    const float* px = pc + (size_t)b*3*NN;
    const float* py = px + NN;
    const float* pz = py + NN;

    float x[8], yv[8], z[8], dmin[8];
#pragma unroll
    for (int j = 0; j < 8; j++) {
        int i = tid + j*512;
        x[j] = px[i]; yv[j] = py[i]; z[j] = pz[i];
        dmin[j] = 1e10f;
    }

    __shared__ float rv[16];
    __shared__ int   ri[16];
    __shared__ int   sfar;

    int far = 0;
    for (int it = 0; it < MM; it++) {
        if (tid == 0) {
            samp[b*MM + it] = far;
            dout[(b*3+0)*MM + it] = px[far];
            dout[(b*3+1)*MM + it] = py[far];
            dout[(b*3+2)*MM + it] = pz[far];
        }
        float cx = px[far], cy = py[far], cz = pz[far];

        float bv = -1.0f; int bi = 0;
#pragma unroll
        for (int j = 0; j < 8; j++) {
            float dx = x[j]  - cx;
            float dy = yv[j] - cy;
            float dz = z[j]  - cz;
            // match mul-then-add rounding (no FMA contraction)
            float d = __fadd_rn(__fadd_rn(__fmul_rn(dx,dx), __fmul_rn(dy,dy)), __fmul_rn(dz,dz));
            float nd = fminf(dmin[j], d);
            dmin[j] = nd;
            if (nd > bv) { bv = nd; bi = tid + j*512; }
        }
        // warp argmax (lowest index on ties)
#pragma unroll
        for (int off = 16; off > 0; off >>= 1) {
            float ov = __shfl_down_sync(0xffffffffu, bv, off);
            int   oi = __shfl_down_sync(0xffffffffu, bi, off);
            if (ov > bv || (ov == bv && oi < bi)) { bv = ov; bi = oi; }
        }
        int w = tid >> 5;
        if ((tid & 31) == 0) { rv[w] = bv; ri[w] = bi; }
        __syncthreads();
        if (w == 0) {
            float v2 = (tid < 16) ? rv[tid] : -2.0f;
            int   i2 = (tid < 16) ? ri[tid] : (1 << 30);
#pragma unroll
            for (int off = 8; off > 0; off >>= 1) {
                float ov = __shfl_down_sync(0xffffffffu, v2, off);
                int   oi = __shfl_down_sync(0xffffffffu, i2, off);
                if (ov > v2 || (ov == v2 && oi < i2)) { v2 = ov; i2 = oi; }
            }
            if (tid == 0) sfar = i2;
        }
        __syncthreads();
        far = sfar;
    }
}

// ---------------- Ball query: warp per center, ordered first-K via ballot ----------------
__global__ __launch_bounds__(256) void ballquery_kernel(const float* __restrict__ pc,
                                                        const int* __restrict__ samp,
                                                        int* __restrict__ gidx,
                                                        float r2, int K)
{
    extern __shared__ float sh[];
    float* sx = sh;
    float* sy = sh + NN;
    float* sz = sh + 2*NN;

    int b = blockIdx.x;
    const float* px = pc + (size_t)b*3*NN;
    for (int i = threadIdx.x; i < NN; i += blockDim.x) {
        sx[i] = px[i]; sy[i] = px[NN + i]; sz[i] = px[2*NN + i];
    }
    __syncthreads();

    int lane = threadIdx.x & 31;
    int wid  = threadIdx.x >> 5;           // 8 warps
    int mstart = blockIdx.y * 64;          // gridDim.y = 16 slices

    for (int m = mstart + wid; m < mstart + 64; m += 8) {
        int ci = samp[b*MM + m];
        float cx = sx[ci], cy = sy[ci], cz = sz[ci];
        int cnt = 0, firstIdx = -1;
        int* outp = gidx + ((size_t)(b*MM + m))*K;

        for (int base = 0; base < NN && cnt < K; base += 32) {
            int i = base + lane;
            float dx = sx[i] - cx;
            float dy = sy[i] - cy;
            float dz = sz[i] - cz;
            float d = __fadd_rn(__fadd_rn(__fmul_rn(dx,dx), __fmul_rn(dy,dy)), __fmul_rn(dz,dz));
            bool ok = d < r2;
            unsigned mask = __ballot_sync(0xffffffffu, ok);
            if (firstIdx < 0 && mask) firstIdx = base + __ffs(mask) - 1;
            int pos = cnt + __popc(mask & ((1u << lane) - 1u));
            if (ok && pos < K) outp[pos] = i;
            cnt = min(K, cnt + __popc(mask));
        }
        for (int p2 = cnt + lane; p2 < K; p2 += 32) outp[p2] = firstIdx;
    }
}

// ---------------- Tiled 1x1-conv GEMM; optional fused gather / fused BN+ReLU input ----------------
template<bool GATHER>
__global__ __launch_bounds__(256) void conv_kernel(
    const float* __restrict__ xin, const float* __restrict__ W, const float* __restrict__ bias,
    const float* __restrict__ bns, const float* __restrict__ bnt,
    float* __restrict__ y, int cin, int P,
    const float* __restrict__ pc, const float* __restrict__ feat,
    const float* __restrict__ newpc, const int* __restrict__ gidx,
    int mkshift, int kshift)
{
    __shared__ __align__(16) float xs[16][128];
    __shared__ __align__(16) float ws[16][32];
    __shared__ float ssA[128], stA[128];
    __shared__ int   sidx[128];

    int tx = threadIdx.x, ty = threadIdx.y;
    int t  = ty*32 + tx;
    int pblock = blockIdx.x * 128;
    int oblock = blockIdx.y * 32;

    if (GATHER) {
        if (t < 128) sidx[t] = gidx[pblock + t];
    } else {
        if (t < cin) { ssA[t] = bns[t]; stA[t] = bnt[t]; }
    }
    __syncthreads();

    float acc[4][4];
#pragma unroll
    for (int i = 0; i < 4; i++)
#pragma unroll
        for (int j = 0; j < 4; j++) acc[i][j] = 0.0f;

    for (int c0 = 0; c0 < cin; c0 += 16) {
        __syncthreads();   // previous tile fully consumed
#pragma unroll
        for (int r = 0; r < 8; r++) {
            int e  = t + r*256;
            int cc = e >> 7, pp = e & 127;
            int c  = c0 + cc;
            float v = 0.0f;
            if (c < cin) {
                if (GATHER) {
                    int p   = pblock + pp;
                    int bb  = p >> mkshift;
                    int mm  = (p >> kshift) & (MM - 1);
                    int idx = sidx[pp];
                    if (c < 3)
                        v = pc[(size_t)(bb*3 + c)*NN + idx] - newpc[(size_t)(bb*3 + c)*MM + mm];
                    else
                        v = feat[(size_t)((bb << 6) + (c - 3))*NN + idx];
                } else {
                    v = xin[(size_t)c*P + pblock + pp];
                    v = fmaxf(v*ssA[c] + stA[c], 0.0f);
                }
            }
            xs[cc][pp] = v;
        }
#pragma unroll
        for (int r = 0; r < 2; r++) {
            int e  = t + r*256;
            int cc = e >> 5, oo = e & 31;
            int c  = c0 + cc;
            ws[cc][oo] = (c < cin) ? W[(size_t)(oblock + oo)*cin + c] : 0.0f;
        }
        __syncthreads();
#pragma unroll
        for (int cc = 0; cc < 16; cc++) {
            float4 xv = *(const float4*)&xs[cc][tx*4];
            float4 wv = *(const float4*)&ws[cc][ty*4];
            acc[0][0] += wv.x*xv.x; acc[0][1] += wv.x*xv.y; acc[0][2] += wv.x*xv.z; acc[0][3] += wv.x*xv.w;
            acc[1][0] += wv.y*xv.x; acc[1][1] += wv.y*xv.y; acc[1][2] += wv.y*xv.z; acc[1][3] += wv.y*xv.w;
            acc[2][0] += wv.z*xv.x; acc[2][1] += wv.z*xv.y; acc[2][2] += wv.z*xv.z; acc[2][3] += wv.z*xv.w;
            acc[3][0] += wv.w*xv.x; acc[3][1] += wv.w*xv.y; acc[3][2] += wv.w*xv.z; acc[3][3] += wv.w*xv.w;
        }
    }

#pragma unroll
    for (int i = 0; i < 4; i++) {
        int o = oblock + ty*4 + i;
        float bs = bias[o];
        float4 r4 = make_float4(acc[i][0]+bs, acc[i][1]+bs, acc[i][2]+bs, acc[i][3]+bs);
        *(float4*)&y[(size_t)o*P + pblock + tx*4] = r4;
    }
}

// ---------------- Per-channel BN stats -> (scale, shift); deterministic, no atomics ----------------
__global__ __launch_bounds__(512) void stats_kernel(const float* __restrict__ y, int P,
                                                    const float* __restrict__ gamma,
                                                    const float* __restrict__ beta,
                                                    float* __restrict__ s, float* __restrict__ t)
{
    int c = blockIdx.x;
    const float* p = y + (size_t)c*P;
    float sum = 0.0f, sum2 = 0.0f;
    for (int i = threadIdx.x*4; i < P; i += blockDim.x*4) {
        float4 v = *(const float4*)(p + i);
        sum  += (v.x + v.y) + (v.z + v.w);
        sum2 += (v.x*v.x + v.y*v.y) + (v.z*v.z + v.w*v.w);
    }
#pragma unroll
    for (int off = 16; off > 0; off >>= 1) {
        sum  += __shfl_down_sync(0xffffffffu, sum,  off);
        sum2 += __shfl_down_sync(0xffffffffu, sum2, off);
    }
    __shared__ float a[16], a2[16];
    int lane = threadIdx.x & 31, w = threadIdx.x >> 5;
    if (lane == 0) { a[w] = sum; a2[w] = sum2; }
    __syncthreads();
    if (threadIdx.x < 16) {
        sum = a[threadIdx.x]; sum2 = a2[threadIdx.x];
#pragma unroll
        for (int off = 8; off > 0; off >>= 1) {
            sum  += __shfl_down_sync(0xffffu, sum,  off);
            sum2 += __shfl_down_sync(0xffffu, sum2, off);
        }
        if (threadIdx.x == 0) {
            float inv = 1.0f / (float)P;
            float mu  = sum * inv;
            float var = sum2 * inv - mu*mu;
            float rs  = 1.0f / sqrtf(var + 1e-5f);
            float sc  = gamma[c] * rs;
            s[c] = sc;
            t[c] = beta[c] - mu * sc;
        }
    }
}

// ---------------- Max-pool over K with fused BN+ReLU ----------------
__global__ __launch_bounds__(256) void maxpool_kernel(const float* __restrict__ y,
                                                      const float* __restrict__ s,
                                                      const float* __restrict__ t,
                                                      float* __restrict__ out,
                                                      int K, int chbase)
{
    int gid = blockIdx.x*256 + threadIdx.x;           // 128 * 16384 outputs
    int o  = gid >> 14;
    int bm = gid & 16383;
    const float* p = y + ((size_t)o*(BB*MM) + bm)*K;
    float sc = s[o], tc = t[o];
    float mx = 0.0f;                                   // ReLU floor
    for (int k = 0; k < K; k += 4) {
        float4 v = *(const float4*)(p + k);
        mx = fmaxf(mx, v.x*sc + tc);
        mx = fmaxf(mx, v.y*sc + tc);
        mx = fmaxf(mx, v.z*sc + tc);
        mx = fmaxf(mx, v.w*sc + tc);
    }
    int b = bm >> 10, m = bm & 1023;
    out[OUT_OFS + ((size_t)(b*256 + chbase + o))*MM + m] = mx;
}

// ---------------- host launch sequence ----------------
extern "C" void kernel_launch(void* const* d_in, const int* in_sizes, int n_in,
                              void* d_out, int out_size)
{
    const float* pc   = (const float*)d_in[0];
    const float* feat = (const float*)d_in[1];
    const float *Wp[6], *bp[6], *gp[6], *bep[6];
    for (int i = 0; i < 6; i++) {
        Wp[i]  = (const float*)d_in[2 + 4*i];
        bp[i]  = (const float*)d_in[3 + 4*i];
        gp[i]  = (const float*)d_in[4 + 4*i];
        bep[i] = (const float*)d_in[5 + 4*i];
    }
    float* out = (float*)d_out;

    int *samp, *idx0, *idx1;
    float *bufA, *bufB, *sv, *tv;
    cudaGetSymbolAddress((void**)&samp, g_samp);
    cudaGetSymbolAddress((void**)&idx0, g_idx0);
    cudaGetSymbolAddress((void**)&idx1, g_idx1);
    cudaGetSymbolAddress((void**)&bufA, g_bufA);
    cudaGetSymbolAddress((void**)&bufB, g_bufB);
    cudaGetSymbolAddress((void**)&sv,   g_s);
    cudaGetSymbolAddress((void**)&tv,   g_t);

    const float r2_0 = (float)(0.1*0.1);
    const float r2_1 = (float)(0.2*0.2);

    fps_kernel<<<BB, 512>>>(pc, samp, out);
    ballquery_kernel<<<dim3(BB,16), 256, 3*NN*sizeof(float)>>>(pc, samp, idx0, r2_0, K0);
    ballquery_kernel<<<dim3(BB,16), 256, 3*NN*sizeof(float)>>>(pc, samp, idx1, r2_1, K1);

    dim3 tb(32, 8);

    // -------- branch 0 (r=0.1, K=32): 67 -> 64 -> 64 -> 128 --------
    conv_kernel<true><<<dim3(P0/128, 2), tb>>>(nullptr, Wp[0], bp[0], nullptr, nullptr,
                                               bufA, 67, P0, pc, feat, out, idx0, 15, 5);
    stats_kernel<<<64, 512>>>(bufA, P0, gp[0], bep[0], sv, tv);
    conv_kernel<false><<<dim3(P0/128, 2), tb>>>(bufA, Wp[1], bp[1], sv, tv,
                                                bufB, 64, P0, nullptr, nullptr, nullptr, nullptr, 0, 0);
    stats_kernel<<<64, 512>>>(bufB, P0, gp[1], bep[1], sv, tv);
    conv_kernel<false><<<dim3(P0/128, 4), tb>>>(bufB, Wp[2], bp[2], sv, tv,
                                                bufA, 64, P0, nullptr, nullptr, nullptr, nullptr, 0, 0);
    stats_kernel<<<128, 512>>>(bufA, P0, gp[2], bep[2], sv, tv);
    maxpool_kernel<<<(128*BB*MM)/256, 256>>>(bufA, sv, tv, out, K0, 0);

    // -------- branch 1 (r=0.2, K=64): 67 -> 64 -> 96 -> 128 --------
    conv_kernel<true><<<dim3(P1/128, 2), tb>>>(nullptr, Wp[3], bp[3], nullptr, nullptr,
                                               bufA, 67, P1, pc, feat, out, idx1, 16, 6);
    stats_kernel<<<64, 512>>>(bufA, P1, gp[3], bep[3], sv, tv);
    conv_kernel<false><<<dim3(P1/128, 3), tb>>>(bufA, Wp[4], bp[4], sv, tv,
                                                bufB, 64, P1, nullptr, nullptr, nullptr, nullptr, 0, 0);
    stats_kernel<<<96, 512>>>(bufB, P1, gp[4], bep[4], sv, tv);
    conv_kernel<false><<<dim3(P1/128, 4), tb>>>(bufB, Wp[5], bp[5], sv, tv,
                                                bufA, 96, P1, nullptr, nullptr, nullptr, nullptr, 0, 0);
    stats_kernel<<<128, 512>>>(bufA, P1, gp[5], bep[5], sv, tv);
    maxpool_kernel<<<(128*BB*MM)/256, 256>>>(bufA, sv, tv, out, K1, 128);
}

// round 2
// speedup vs baseline: 1.7799x; 1.7799x over previous
#include <cuda_runtime.h>
#include <cstdint>

#define BB 16
#define NN 4096
#define MM 1024
#define K0 32
#define K1 64
#define P0 (BB*MM*K0)     // 524288
#define P1 (BB*MM*K1)     // 1048576
#define OUT_OFS (BB*3*MM) // 49152

// ---------------- scratch (device globals; no allocation allowed) ----------------
__device__ int   g_samp[BB*MM];
__device__ int   g_idx0[P0];
__device__ int   g_idx1[P1];
__device__ float g_bufA[128*P1];   // 512 MB
__device__ float g_bufB[96*P1];    // 384 MB
__device__ float g_s[128];
__device__ float g_t[128];
__device__ float g_ps [128*4096];  // per-block partial sums
__device__ float g_ps2[128*4096];  // per-block partial sumsq
__device__ float g_wt [6*12288];   // transposed zero-padded weights

// ---------------- FPS: one block per batch, coords+dmin in registers ----------------
__global__ __launch_bounds__(512) void fps_kernel(const float* __restrict__ pc,
                                                  int* __restrict__ samp,
                                                  float* __restrict__ dout)
{
    int b   = blockIdx.x;
    int tid = threadIdx.x;
    const float* px = pc + (size_t)b*3*NN;
    const float* py = px + NN;
    const float* pz = py + NN;

    float x[8], yv[8], z[8], dmin[8];
#pragma unroll
    for (int j = 0; j < 8; j++) {
        int i = tid + j*512;
        x[j] = px[i]; yv[j] = py[i]; z[j] = pz[i];
        dmin[j] = 1e10f;
    }

    __shared__ float rv[16];
    __shared__ int   ri[16];
    __shared__ int   sfar;

    int far = 0;
    for (int it = 0; it < MM; it++) {
        if (tid == 0) {
            samp[b*MM + it] = far;
            dout[(b*3+0)*MM + it] = px[far];
            dout[(b*3+1)*MM + it] = py[far];
            dout[(b*3+2)*MM + it] = pz[far];
        }
        float cx = px[far], cy = py[far], cz = pz[far];

        float bv = -1.0f; int bi = 0;
#pragma unroll
        for (int j = 0; j < 8; j++) {
            float dx = x[j]  - cx;
            float dy = yv[j] - cy;
            float dz = z[j]  - cz;
            float d = __fadd_rn(__fadd_rn(__fmul_rn(dx,dx), __fmul_rn(dy,dy)), __fmul_rn(dz,dz));
            float nd = fminf(dmin[j], d);
            dmin[j] = nd;
            if (nd > bv) { bv = nd; bi = tid + j*512; }
        }
#pragma unroll
        for (int off = 16; off > 0; off >>= 1) {
            float ov = __shfl_down_sync(0xffffffffu, bv, off);
            int   oi = __shfl_down_sync(0xffffffffu, bi, off);
            if (ov > bv || (ov == bv && oi < bi)) { bv = ov; bi = oi; }
        }
        int w = tid >> 5;
        if ((tid & 31) == 0) { rv[w] = bv; ri[w] = bi; }
        __syncthreads();
        if (w == 0) {
            float v2 = (tid < 16) ? rv[tid] : -2.0f;
            int   i2 = (tid < 16) ? ri[tid] : (1 << 30);
#pragma unroll
            for (int off = 8; off > 0; off >>= 1) {
                float ov = __shfl_down_sync(0xffffffffu, v2, off);
                int   oi = __shfl_down_sync(0xffffffffu, i2, off);
                if (ov > v2 || (ov == v2 && oi < i2)) { v2 = ov; i2 = oi; }
            }
            if (tid == 0) sfar = i2;
        }
        __syncthreads();
        far = sfar;
    }
}

// ---------------- Ball query: warp per center, ordered first-K via ballot ----------------
__global__ __launch_bounds__(256) void ballquery_kernel(const float* __restrict__ pc,
                                                        const int* __restrict__ samp,
                                                        int* __restrict__ gidx,
                                                        float r2, int K)
{
    extern __shared__ float sh[];
    float* sx = sh;
    float* sy = sh + NN;
    float* sz = sh + 2*NN;

    int b = blockIdx.x;
    const float* px = pc + (size_t)b*3*NN;
    for (int i = threadIdx.x; i < NN; i += blockDim.x) {
        sx[i] = px[i]; sy[i] = px[NN + i]; sz[i] = px[2*NN + i];
    }
    __syncthreads();

    int lane = threadIdx.x & 31;
    int wid  = threadIdx.x >> 5;
    int mstart = blockIdx.y * 64;

    for (int m = mstart + wid; m < mstart + 64; m += 8) {
        int ci = samp[b*MM + m];
        float cx = sx[ci], cy = sy[ci], cz = sz[ci];
        int cnt = 0, firstIdx = -1;
        int* outp = gidx + ((size_t)(b*MM + m))*K;

        for (int base = 0; base < NN && cnt < K; base += 32) {
            int i = base + lane;
            float dx = sx[i] - cx;
            float dy = sy[i] - cy;
            float dz = sz[i] - cz;
            float d = __fadd_rn(__fadd_rn(__fmul_rn(dx,dx), __fmul_rn(dy,dy)), __fmul_rn(dz,dz));
            bool ok = d < r2;
            unsigned mask = __ballot_sync(0xffffffffu, ok);
            if (firstIdx < 0 && mask) firstIdx = base + __ffs(mask) - 1;
            int pos = cnt + __popc(mask & ((1u << lane) - 1u));
            if (ok && pos < K) outp[pos] = i;
            cnt = min(K, cnt + __popc(mask));
        }
        for (int p2 = cnt + lane; p2 < K; p2 += 32) outp[p2] = firstIdx;
    }
}

// ---------------- weight transpose + zero-pad: Wt[c][o], c < cpad ----------------
__global__ void wtranspose_kernel(const float* __restrict__ W, float* __restrict__ Wt,
                                  int cin, int cpad, int cout)
{
    int total = cpad * cout;
    for (int e = blockIdx.x*256 + threadIdx.x; e < total; e += gridDim.x*256) {
        int c = e / cout, o = e - c*cout;
        Wt[e] = (c < cin) ? W[o*cin + c] : 0.0f;
    }
}

// ---------------- Tiled GEMM: 32 out x 256 pos per block, double buffered ----------------
// thread (tx,ty): 4 outs (ty*4..) x 8 positions (tx*4.. and 128+tx*4..)
template<bool GATHER>
__global__ __launch_bounds__(256) void conv_kernel(
    const float* __restrict__ xin, const float* __restrict__ Wt,
    const float* __restrict__ bias,
    const float* __restrict__ bns, const float* __restrict__ bnt,
    float* __restrict__ y, float* __restrict__ ps, float* __restrict__ ps2,
    int cin, int nk, int cout, int P,
    const float* __restrict__ pc, const float* __restrict__ feat,
    const float* __restrict__ newpc, const int* __restrict__ gidx,
    int mkshift, int kshift)
{
    __shared__ __align__(16) float xs[2][16][256];
    __shared__ __align__(16) float ws[2][16][32];
    __shared__ float ssA[96], stA[96];
    __shared__ int sidx[256];

    const int tx = threadIdx.x, ty = threadIdx.y;
    const int t  = ty*32 + tx;
    const int pblock = blockIdx.x * 256;
    const int oblock = blockIdx.y * 32;
    const int nblk = gridDim.x;

    if (GATHER) {
        sidx[t] = gidx[pblock + t];
    } else {
        if (t < cin) { ssA[t] = bns[t]; stA[t] = bnt[t]; }
    }
    __syncthreads();

    int g_bb = 0, g_mm = 0, g_ix = 0;
    if (GATHER) {
        int p = pblock + t;
        g_bb = p >> mkshift;
        g_mm = (p >> kshift) & (MM - 1);
        g_ix = sidx[t];
    }

    float4 xr[4];
    float  gxr[16];
    float4 wr = make_float4(0,0,0,0);

    auto load_x = [&](int kc) {
        int c0 = kc * 16;
        if (GATHER) {
#pragma unroll
            for (int i = 0; i < 16; i++) {
                int c = c0 + i;
                float v = 0.0f;
                if (c < cin) {
                    if (c < 3)
                        v = pc[(size_t)(g_bb*3 + c)*NN + g_ix] - newpc[(size_t)(g_bb*3 + c)*MM + g_mm];
                    else
                        v = feat[(size_t)((g_bb << 6) + (c - 3))*NN + g_ix];
                }
                gxr[i] = v;
            }
        } else {
#pragma unroll
            for (int i = 0; i < 4; i++) {
                int f  = t + i*256;
                int cc = f >> 6, q = f & 63;
                int c  = c0 + cc;
                float4 v = make_float4(0,0,0,0);
                if (c < cin) {
                    v = *(const float4*)&xin[(size_t)c*P + pblock + q*4];
                    float sc = ssA[c], tc = stA[c];
                    v.x = fmaxf(v.x*sc + tc, 0.0f);
                    v.y = fmaxf(v.y*sc + tc, 0.0f);
                    v.z = fmaxf(v.z*sc + tc, 0.0f);
                    v.w = fmaxf(v.w*sc + tc, 0.0f);
                }
                xr[i] = v;
            }
        }
    };
    auto load_w = [&](int kc) {
        if (t < 128) {
            int cc = t >> 3, o4 = t & 7;
            wr = *(const float4*)&Wt[(size_t)(kc*16 + cc)*cout + oblock + o4*4];
        }
    };
    auto store_stage = [&](int buf) {
        if (GATHER) {
#pragma unroll
            for (int i = 0; i < 16; i++) xs[buf][i][t] = gxr[i];
        } else {
#pragma unroll
            for (int i = 0; i < 4; i++) {
                int f  = t + i*256;
                int cc = f >> 6, q = f & 63;
                *(float4*)&xs[buf][cc][q*4] = xr[i];
            }
        }
        if (t < 128) {
            int cc = t >> 3, o4 = t & 7;
            *(float4*)&ws[buf][cc][o4*4] = wr;
        }
    };

    float acc[4][8];
#pragma unroll
    for (int o = 0; o < 4; o++)
#pragma unroll
        for (int p = 0; p < 8; p++) acc[o][p] = 0.0f;

    load_x(0); load_w(0); store_stage(0);
    __syncthreads();

    for (int kc = 0; kc < nk; kc++) {
        int buf = kc & 1;
        if (kc + 1 < nk) { load_x(kc + 1); load_w(kc + 1); }
#pragma unroll
        for (int cc = 0; cc < 16; cc++) {
            float4 w = *(const float4*)&ws[buf][cc][ty*4];
            float4 a = *(const float4*)&xs[buf][cc][tx*4];
            float4 b2 = *(const float4*)&xs[buf][cc][128 + tx*4];
            acc[0][0] += w.x*a.x;  acc[0][1] += w.x*a.y;  acc[0][2] += w.x*a.z;  acc[0][3] += w.x*a.w;
            acc[0][4] += w.x*b2.x; acc[0][5] += w.x*b2.y; acc[0][6] += w.x*b2.z; acc[0][7] += w.x*b2.w;
            acc[1][0] += w.y*a.x;  acc[1][1] += w.y*a.y;  acc[1][2] += w.y*a.z;  acc[1][3] += w.y*a.w;
            acc[1][4] += w.y*b2.x; acc[1][5] += w.y*b2.y; acc[1][6] += w.y*b2.z; acc[1][7] += w.y*b2.w;
            acc[2][0] += w.z*a.x;  acc[2][1] += w.z*a.y;  acc[2][2] += w.z*a.z;  acc[2][3] += w.z*a.w;
            acc[2][4] += w.z*b2.x; acc[2][5] += w.z*b2.y; acc[2][6] += w.z*b2.z; acc[2][7] += w.z*b2.w;
            acc[3][0] += w.w*a.x;  acc[3][1] += w.w*a.y;  acc[3][2] += w.w*a.z;  acc[3][3] += w.w*a.w;
            acc[3][4] += w.w*b2.x; acc[3][5] += w.w*b2.y; acc[3][6] += w.w*b2.z; acc[3][7] += w.w*b2.w;
        }
        if (kc + 1 < nk) store_stage(buf ^ 1);
        __syncthreads();
    }

    // epilogue: bias, store, per-channel partial stats (warp = fixed ty)
    int pbase0 = pblock + tx*4;
#pragma unroll
    for (int o = 0; o < 4; o++) {
        int oc = oblock + ty*4 + o;
        float bv = bias[oc];
        float4 r0 = make_float4(acc[o][0]+bv, acc[o][1]+bv, acc[o][2]+bv, acc[o][3]+bv);
        float4 r1 = make_float4(acc[o][4]+bv, acc[o][5]+bv, acc[o][6]+bv, acc[o][7]+bv);
        *(float4*)&y[(size_t)oc*P + pbase0]       = r0;
        *(float4*)&y[(size_t)oc*P + pbase0 + 128] = r1;
        float s1 = ((r0.x+r0.y)+(r0.z+r0.w)) + ((r1.x+r1.y)+(r1.z+r1.w));
        float s2 = (r0.x*r0.x + r0.y*r0.y + r0.z*r0.z + r0.w*r0.w)
                 + (r1.x*r1.x + r1.y*r1.y + r1.z*r1.z + r1.w*r1.w);
#pragma unroll
        for (int off = 16; off > 0; off >>= 1) {
            s1 += __shfl_down_sync(0xffffffffu, s1, off);
            s2 += __shfl_down_sync(0xffffffffu, s2, off);
        }
        if (tx == 0) {
            ps [(size_t)oc*nblk + blockIdx.x] = s1;
            ps2[(size_t)oc*nblk + blockIdx.x] = s2;
        }
    }
}

// ---------------- finalize BN: reduce partials -> (scale, shift) ----------------
__global__ __launch_bounds__(256) void finalize_kernel(const float* __restrict__ ps,
                                                       const float* __restrict__ ps2,
                                                       int nblk, float invP,
                                                       const float* __restrict__ gamma,
                                                       const float* __restrict__ beta,
                                                       float* __restrict__ s,
                                                       float* __restrict__ t)
{
    int c = blockIdx.x;
    float a = 0.0f, b = 0.0f;
    for (int i = threadIdx.x; i < nblk; i += 256) {
        a += ps [(size_t)c*nblk + i];
        b += ps2[(size_t)c*nblk + i];
    }
#pragma unroll
    for (int off = 16; off > 0; off >>= 1) {
        a += __shfl_down_sync(0xffffffffu, a, off);
        b += __shfl_down_sync(0xffffffffu, b, off);
    }
    __shared__ float sa[8], sb[8];
    int lane = threadIdx.x & 31, w = threadIdx.x >> 5;
    if (lane == 0) { sa[w] = a; sb[w] = b; }
    __syncthreads();
    if (threadIdx.x < 8) {
        a = sa[threadIdx.x]; b = sb[threadIdx.x];
#pragma unroll
        for (int off = 4; off > 0; off >>= 1) {
            a += __shfl_down_sync(0xffu, a, off);
            b += __shfl_down_sync(0xffu, b, off);
        }
        if (threadIdx.x == 0) {
            float mu  = a * invP;
            float var = b * invP - mu*mu;
            float rs  = 1.0f / sqrtf(var + 1e-5f);
            float sc  = gamma[c] * rs;
            s[c] = sc;
            t[c] = beta[c] - mu * sc;
        }
    }
}

// ---------------- Max-pool over K with fused BN+ReLU ----------------
__global__ __launch_bounds__(256) void maxpool_kernel(const float* __restrict__ y,
                                                      const float* __restrict__ s,
                                                      const float* __restrict__ t,
                                                      float* __restrict__ out,
                                                      int K, int chbase)
{
    int gid = blockIdx.x*256 + threadIdx.x;
    int o  = gid >> 14;
    int bm = gid & 16383;
    const float* p = y + ((size_t)o*(BB*MM) + bm)*K;
    float sc = s[o], tc = t[o];
    float mx = 0.0f;
    for (int k = 0; k < K; k += 4) {
        float4 v = *(const float4*)(p + k);
        mx = fmaxf(mx, v.x*sc + tc);
        mx = fmaxf(mx, v.y*sc + tc);
        mx = fmaxf(mx, v.z*sc + tc);
        mx = fmaxf(mx, v.w*sc + tc);
    }
    int b = bm >> 10, m = bm & 1023;
    out[OUT_OFS + ((size_t)(b*256 + chbase + o))*MM + m] = mx;
}

// ---------------- host launch sequence ----------------
extern "C" void kernel_launch(void* const* d_in, const int* in_sizes, int n_in,
                              void* d_out, int out_size)
{
    const float* pc   = (const float*)d_in[0];
    const float* feat = (const float*)d_in[1];
    const float *Wp[6], *bp[6], *gp[6], *bep[6];
    for (int i = 0; i < 6; i++) {
        Wp[i]  = (const float*)d_in[2 + 4*i];
        bp[i]  = (const float*)d_in[3 + 4*i];
        gp[i]  = (const float*)d_in[4 + 4*i];
        bep[i] = (const float*)d_in[5 + 4*i];
    }
    float* out = (float*)d_out;

    int *samp, *idx0, *idx1;
    float *bufA, *bufB, *sv, *tv, *ps, *ps2, *wt;
    cudaGetSymbolAddress((void**)&samp, g_samp);
    cudaGetSymbolAddress((void**)&idx0, g_idx0);
    cudaGetSymbolAddress((void**)&idx1, g_idx1);
    cudaGetSymbolAddress((void**)&bufA, g_bufA);
    cudaGetSymbolAddress((void**)&bufB, g_bufB);
    cudaGetSymbolAddress((void**)&sv,   g_s);
    cudaGetSymbolAddress((void**)&tv,   g_t);
    cudaGetSymbolAddress((void**)&ps,   g_ps);
    cudaGetSymbolAddress((void**)&ps2,  g_ps2);
    cudaGetSymbolAddress((void**)&wt,   g_wt);

    const float r2_0 = (float)(0.1*0.1);
    const float r2_1 = (float)(0.2*0.2);

    // layer params: cin, cpad (nk*16), cout
    const int cins[6]  = {67, 64, 64, 67, 64, 96};
    const int cpads[6] = {80, 64, 64, 80, 64, 96};
    const int couts[6] = {64, 64, 128, 64, 96, 128};

    for (int l = 0; l < 6; l++)
        wtranspose_kernel<<<12, 256>>>(Wp[l], wt + l*12288, cins[l], cpads[l], couts[l]);

    fps_kernel<<<BB, 512>>>(pc, samp, out);
    ballquery_kernel<<<dim3(BB,16), 256, 3*NN*sizeof(float)>>>(pc, samp, idx0, r2_0, K0);
    ballquery_kernel<<<dim3(BB,16), 256, 3*NN*sizeof(float)>>>(pc, samp, idx1, r2_1, K1);

    dim3 tb(32, 8);
    const int nbx0 = P0/256, nbx1 = P1/256;

    // -------- branch 0 (K=32): 67 -> 64 -> 64 -> 128 --------
    conv_kernel<true><<<dim3(nbx0, 2), tb>>>(nullptr, wt + 0*12288, bp[0], nullptr, nullptr,
        bufA, ps, ps2, 67, 5, 64, P0, pc, feat, out, idx0, 15, 5);
    finalize_kernel<<<64, 256>>>(ps, ps2, nbx0, 1.0f/(float)P0, gp[0], bep[0], sv, tv);
    conv_kernel<false><<<dim3(nbx0, 2), tb>>>(bufA, wt + 1*12288, bp[1], sv, tv,
        bufB, ps, ps2, 64, 4, 64, P0, nullptr, nullptr, nullptr, nullptr, 0, 0);
    finalize_kernel<<<64, 256>>>(ps, ps2, nbx0, 1.0f/(float)P0, gp[1], bep[1], sv, tv);
    conv_kernel<false><<<dim3(nbx0, 4), tb>>>(bufB, wt + 2*12288, bp[2], sv, tv,
        bufA, ps, ps2, 64, 4, 128, P0, nullptr, nullptr, nullptr, nullptr, 0, 0);
    finalize_kernel<<<128, 256>>>(ps, ps2, nbx0, 1.0f/(float)P0, gp[2], bep[2], sv, tv);
    maxpool_kernel<<<(128*BB*MM)/256, 256>>>(bufA, sv, tv, out, K0, 0);

    // -------- branch 1 (K=64): 67 -> 64 -> 96 -> 128 --------
    conv_kernel<true><<<dim3(nbx1, 2), tb>>>(nullptr, wt + 3*12288, bp[3], nullptr, nullptr,
        bufA, ps, ps2, 67, 5, 64, P1, pc, feat, out, idx1, 16, 6);
    finalize_kernel<<<64, 256>>>(ps, ps2, nbx1, 1.0f/(float)P1, gp[3], bep[3], sv, tv);
    conv_kernel<false><<<dim3(nbx1, 3), tb>>>(bufA, wt + 4*12288, bp[4], sv, tv,
        bufB, ps, ps2, 64, 4, 96, P1, nullptr, nullptr, nullptr, nullptr, 0, 0);
    finalize_kernel<<<96, 256>>>(ps, ps2, nbx1, 1.0f/(float)P1, gp[4], bep[4], sv, tv);
    conv_kernel<false><<<dim3(nbx1, 4), tb>>>(bufB, wt + 5*12288, bp[5], sv, tv,
        bufA, ps, ps2, 96, 6, 128, P1, nullptr, nullptr, nullptr, nullptr, 0, 0);
    finalize_kernel<<<128, 256>>>(ps, ps2, nbx1, 1.0f/(float)P1, gp[5], bep[5], sv, tv);
    maxpool_kernel<<<(128*BB*MM)/256, 256>>>(bufA, sv, tv, out, K1, 128);
}

// round 3
// speedup vs baseline: 2.4398x; 1.3707x over previous
#include <cuda_runtime.h>
#include <cstdint>

#define BB 16
#define NN 4096
#define MM 1024
#define K0 32
#define K1 64
#define P0 (BB*MM*K0)     // 524288
#define P1 (BB*MM*K1)     // 1048576
#define OUT_OFS (BB*3*MM) // 49152
#define GCOUNT (BB*MM)    // 16384 pool groups per channel

// ---------------- scratch (device globals; no allocation allowed) ----------------
__device__ int   g_samp[BB*MM];
__device__ int   g_idx0[P0];
__device__ int   g_idx1[P1];
__device__ float g_bufA[64*P1];    // 256 MB
__device__ float g_bufB[96*P1];    // 384 MB
__device__ float g_ft[BB*NN*64];   // transposed features (B,N,64)
__device__ float g_s[128];
__device__ float g_t[128];
__device__ float g_ps [128*4096];
__device__ float g_ps2[128*4096];
__device__ float g_pmax[128*GCOUNT];
__device__ float g_pmin[128*GCOUNT];
__device__ float g_wt [6*12288];

struct WPtrs { const float* w[6]; };

// ---------------- combined weight transpose + channel permute ----------------
__global__ void wtr_kernel(WPtrs wp, float* __restrict__ wt)
{
    const int cins[6]  = {67, 64, 64, 67, 64, 96};
    const int cpads[6] = {80, 64, 64, 80, 64, 96};
    const int couts[6] = {64, 64, 128, 64, 96, 128};
    const int gat[6]   = {1, 0, 0, 1, 0, 0};
    int l = blockIdx.x;
    const float* W = wp.w[l];
    int cin = cins[l], cpad = cpads[l], cout = couts[l];
    float* dst = wt + l*12288;
    int total = cpad * cout;
    for (int e = threadIdx.x; e < total; e += 256) {
        int c = e / cout, o = e - c*cout;
        int src;
        if (gat[l]) src = (c < 64) ? c + 3 : (c < 67 ? c - 64 : -1);
        else        src = (c < cin) ? c : -1;
        dst[e] = (src >= 0) ? W[o*cin + src] : 0.0f;
    }
}

// ---------------- feature transpose: (B,64,N) -> (B,N,64) ----------------
__global__ __launch_bounds__(256) void ftr_kernel(const float* __restrict__ feat,
                                                  float* __restrict__ ft)
{
    __shared__ float tile[32][33];
    int b = blockIdx.z, c0 = blockIdx.y*32, n0 = blockIdx.x*32;
    int tx = threadIdx.x, ty = threadIdx.y;
#pragma unroll
    for (int k = 0; k < 4; k++) {
        int c = c0 + ty + k*8;
        tile[ty + k*8][tx] = feat[(size_t)(b*64 + c)*NN + n0 + tx];
    }
    __syncthreads();
#pragma unroll
    for (int k = 0; k < 4; k++) {
        int n = n0 + ty + k*8;
        ft[((size_t)b*NN + n)*64 + c0 + tx] = tile[tx][ty + k*8];
    }
}

// ---------------- FPS: one block per batch, coords+dmin in registers ----------------
__global__ __launch_bounds__(512) void fps_kernel(const float* __restrict__ pc,
                                                  int* __restrict__ samp,
                                                  float* __restrict__ dout)
{
    int b   = blockIdx.x;
    int tid = threadIdx.x;
    const float* px = pc + (size_t)b*3*NN;
    const float* py = px + NN;
    const float* pz = py + NN;

    float x[8], yv[8], z[8], dmin[8];
#pragma unroll
    for (int j = 0; j < 8; j++) {
        int i = tid + j*512;
        x[j] = px[i]; yv[j] = py[i]; z[j] = pz[i];
        dmin[j] = 1e10f;
    }

    __shared__ float rv[16];
    __shared__ int   ri[16];
    __shared__ int   sfar;

    int far = 0;
    for (int it = 0; it < MM; it++) {
        if (tid == 0) {
            samp[b*MM + it] = far;
            dout[(b*3+0)*MM + it] = px[far];
            dout[(b*3+1)*MM + it] = py[far];
            dout[(b*3+2)*MM + it] = pz[far];
        }
        float cx = px[far], cy = py[far], cz = pz[far];

        float bv = -1.0f; int bi = 0;
#pragma unroll
        for (int j = 0; j < 8; j++) {
            float dx = x[j]  - cx;
            float dy = yv[j] - cy;
            float dz = z[j]  - cz;
            float d = __fadd_rn(__fadd_rn(__fmul_rn(dx,dx), __fmul_rn(dy,dy)), __fmul_rn(dz,dz));
            float nd = fminf(dmin[j], d);
            dmin[j] = nd;
            if (nd > bv) { bv = nd; bi = tid + j*512; }
        }
#pragma unroll
        for (int off = 16; off > 0; off >>= 1) {
            float ov = __shfl_down_sync(0xffffffffu, bv, off);
            int   oi = __shfl_down_sync(0xffffffffu, bi, off);
            if (ov > bv || (ov == bv && oi < bi)) { bv = ov; bi = oi; }
        }
        int w = tid >> 5;
        if ((tid & 31) == 0) { rv[w] = bv; ri[w] = bi; }
        __syncthreads();
        if (w == 0) {
            float v2 = (tid < 16) ? rv[tid] : -2.0f;
            int   i2 = (tid < 16) ? ri[tid] : (1 << 30);
#pragma unroll
            for (int off = 8; off > 0; off >>= 1) {
                float ov = __shfl_down_sync(0xffffffffu, v2, off);
                int   oi = __shfl_down_sync(0xffffffffu, i2, off);
                if (ov > v2 || (ov == v2 && oi < i2)) { v2 = ov; i2 = oi; }
            }
            if (tid == 0) sfar = i2;
        }
        __syncthreads();
        far = sfar;
    }
}

// ---------------- Ball query: warp per center, ordered first-K via ballot ----------------
__global__ __launch_bounds__(256) void ballquery_kernel(const float* __restrict__ pc,
                                                        const int* __restrict__ samp,
                                                        int* __restrict__ gidx,
                                                        float r2, int K)
{
    extern __shared__ float sh[];
    float* sx = sh;
    float* sy = sh + NN;
    float* sz = sh + 2*NN;

    int b = blockIdx.x;
    const float* px = pc + (size_t)b*3*NN;
    for (int i = threadIdx.x; i < NN; i += blockDim.x) {
        sx[i] = px[i]; sy[i] = px[NN + i]; sz[i] = px[2*NN + i];
    }
    __syncthreads();

    int lane = threadIdx.x & 31;
    int wid  = threadIdx.x >> 5;
    int mstart = blockIdx.y * 64;

    for (int m = mstart + wid; m < mstart + 64; m += 8) {
        int ci = samp[b*MM + m];
        float cx = sx[ci], cy = sy[ci], cz = sz[ci];
        int cnt = 0, firstIdx = -1;
        int* outp = gidx + ((size_t)(b*MM + m))*K;

        for (int base = 0; base < NN && cnt < K; base += 32) {
            int i = base + lane;
            float dx = sx[i] - cx;
            float dy = sy[i] - cy;
            float dz = sz[i] - cz;
            float d = __fadd_rn(__fadd_rn(__fmul_rn(dx,dx), __fmul_rn(dy,dy)), __fmul_rn(dz,dz));
            bool ok = d < r2;
            unsigned mask = __ballot_sync(0xffffffffu, ok);
            if (firstIdx < 0 && mask) firstIdx = base + __ffs(mask) - 1;
            int pos = cnt + __popc(mask & ((1u << lane) - 1u));
            if (ok && pos < K) outp[pos] = i;
            cnt = min(K, cnt + __popc(mask));
        }
        for (int p2 = cnt + lane; p2 < K; p2 += 32) outp[p2] = firstIdx;
    }
}

// ---------------- Tiled GEMM: 32 out x 256 pos, double buffered ----------------
// GATHER: layer-1 fused gather (channels = [feat 0..63, xyz 64..66], cpad 80)
// POOL:   last layer; no y store; per-group max/min for fused maxpool
template<bool GATHER, bool POOL>
__global__ __launch_bounds__(256) void conv_kernel(
    const float* __restrict__ xin, const float* __restrict__ Wt,
    const float* __restrict__ bias,
    const float* __restrict__ bns, const float* __restrict__ bnt,
    float* __restrict__ y, float* __restrict__ ps, float* __restrict__ ps2,
    float* __restrict__ pmax, float* __restrict__ pmin,
    int cin, int nk, int cout, int P, int K,
    const float* __restrict__ pc, const float* __restrict__ ft,
    const float* __restrict__ newpc, const int* __restrict__ gidx,
    int mkshift, int kshift)
{
    __shared__ __align__(16) float xs[2][16][256];
    __shared__ __align__(16) float ws[2][16][32];
    __shared__ float ssA[96], stA[96];
    __shared__ int sidx[256];

    const int tx = threadIdx.x, ty = threadIdx.y;
    const int t  = ty*32 + tx;
    const int pblock = blockIdx.x * 256;
    const int oblock = blockIdx.y * 32;
    const int nblk = gridDim.x;

    if (GATHER) {
        sidx[t] = gidx[pblock + t];
    } else {
        if (t < cin) { ssA[t] = bns[t]; stA[t] = bnt[t]; }
    }
    __syncthreads();

    int g_bb = 0, g_mm = 0, g_ix = 0;
    size_t g_fb = 0;
    if (GATHER) {
        int p = pblock + t;
        g_bb = p >> mkshift;
        g_mm = (p >> kshift) & (MM - 1);
        g_ix = sidx[t];
        g_fb = ((size_t)g_bb*NN + g_ix)*64;
    }

    float4 xr[4];
    float  gxr[16];
    float4 wr = make_float4(0,0,0,0);

    auto load_x = [&](int kc) {
        if (GATHER) {
            if (kc < 4) {
#pragma unroll
                for (int j = 0; j < 4; j++) {
                    float4 v = *(const float4*)&ft[g_fb + kc*16 + j*4];
                    gxr[j*4+0] = v.x; gxr[j*4+1] = v.y; gxr[j*4+2] = v.z; gxr[j*4+3] = v.w;
                }
            } else {
#pragma unroll
                for (int i = 0; i < 16; i++) gxr[i] = 0.0f;
#pragma unroll
                for (int d = 0; d < 3; d++)
                    gxr[d] = pc[(size_t)(g_bb*3 + d)*NN + g_ix] - newpc[(size_t)(g_bb*3 + d)*MM + g_mm];
            }
        } else {
            int c0 = kc * 16;
#pragma unroll
            for (int i = 0; i < 4; i++) {
                int f  = t + i*256;
                int cc = f >> 6, q = f & 63;
                int c  = c0 + cc;
                float4 v = *(const float4*)&xin[(size_t)c*P + pblock + q*4];
                float sc = ssA[c], tc = stA[c];
                v.x = fmaxf(v.x*sc + tc, 0.0f);
                v.y = fmaxf(v.y*sc + tc, 0.0f);
                v.z = fmaxf(v.z*sc + tc, 0.0f);
                v.w = fmaxf(v.w*sc + tc, 0.0f);
                xr[i] = v;
            }
        }
    };
    auto load_w = [&](int kc) {
        if (t < 128) {
            int cc = t >> 3, o4 = t & 7;
            wr = *(const float4*)&Wt[(size_t)(kc*16 + cc)*cout + oblock + o4*4];
        }
    };
    auto store_stage = [&](int buf) {
        if (GATHER) {
#pragma unroll
            for (int i = 0; i < 16; i++) xs[buf][i][t] = gxr[i];
        } else {
#pragma unroll
            for (int i = 0; i < 4; i++) {
                int f  = t + i*256;
                int cc = f >> 6, q = f & 63;
                *(float4*)&xs[buf][cc][q*4] = xr[i];
            }
        }
        if (t < 128) {
            int cc = t >> 3, o4 = t & 7;
            *(float4*)&ws[buf][cc][o4*4] = wr;
        }
    };

    float acc[4][8];
#pragma unroll
    for (int o = 0; o < 4; o++)
#pragma unroll
        for (int p = 0; p < 8; p++) acc[o][p] = 0.0f;

    load_x(0); load_w(0); store_stage(0);
    __syncthreads();

    for (int kc = 0; kc < nk; kc++) {
        int buf = kc & 1;
        if (kc + 1 < nk) { load_x(kc + 1); load_w(kc + 1); }
#pragma unroll
        for (int cc = 0; cc < 16; cc++) {
            float4 w  = *(const float4*)&ws[buf][cc][ty*4];
            float4 a  = *(const float4*)&xs[buf][cc][tx*4];
            float4 b2 = *(const float4*)&xs[buf][cc][128 + tx*4];
            acc[0][0] += w.x*a.x;  acc[0][1] += w.x*a.y;  acc[0][2] += w.x*a.z;  acc[0][3] += w.x*a.w;
            acc[0][4] += w.x*b2.x; acc[0][5] += w.x*b2.y; acc[0][6] += w.x*b2.z; acc[0][7] += w.x*b2.w;
            acc[1][0] += w.y*a.x;  acc[1][1] += w.y*a.y;  acc[1][2] += w.y*a.z;  acc[1][3] += w.y*a.w;
            acc[1][4] += w.y*b2.x; acc[1][5] += w.y*b2.y; acc[1][6] += w.y*b2.z; acc[1][7] += w.y*b2.w;
            acc[2][0] += w.z*a.x;  acc[2][1] += w.z*a.y;  acc[2][2] += w.z*a.z;  acc[2][3] += w.z*a.w;
            acc[2][4] += w.z*b2.x; acc[2][5] += w.z*b2.y; acc[2][6] += w.z*b2.z; acc[2][7] += w.z*b2.w;
            acc[3][0] += w.w*a.x;  acc[3][1] += w.w*a.y;  acc[3][2] += w.w*a.z;  acc[3][3] += w.w*a.w;
            acc[3][4] += w.w*b2.x; acc[3][5] += w.w*b2.y; acc[3][6] += w.w*b2.z; acc[3][7] += w.w*b2.w;
        }
        if (kc + 1 < nk) store_stage(buf ^ 1);
        __syncthreads();
    }

    int pbase0 = pblock + tx*4;
#pragma unroll
    for (int o = 0; o < 4; o++) {
        int oc = oblock + ty*4 + o;
        float bv = bias[oc];
        float4 r0 = make_float4(acc[o][0]+bv, acc[o][1]+bv, acc[o][2]+bv, acc[o][3]+bv);
        float4 r1 = make_float4(acc[o][4]+bv, acc[o][5]+bv, acc[o][6]+bv, acc[o][7]+bv);
        if (!POOL) {
            *(float4*)&y[(size_t)oc*P + pbase0]       = r0;
            *(float4*)&y[(size_t)oc*P + pbase0 + 128] = r1;
        }
        float s1 = ((r0.x+r0.y)+(r0.z+r0.w)) + ((r1.x+r1.y)+(r1.z+r1.w));
        float s2 = (r0.x*r0.x + r0.y*r0.y + r0.z*r0.z + r0.w*r0.w)
                 + (r1.x*r1.x + r1.y*r1.y + r1.z*r1.z + r1.w*r1.w);
#pragma unroll
        for (int off = 16; off > 0; off >>= 1) {
            s1 += __shfl_down_sync(0xffffffffu, s1, off);
            s2 += __shfl_down_sync(0xffffffffu, s2, off);
        }
        if (tx == 0) {
            ps [(size_t)oc*nblk + blockIdx.x] = s1;
            ps2[(size_t)oc*nblk + blockIdx.x] = s2;
        }
        if (POOL) {
            float mxA = fmaxf(fmaxf(r0.x, r0.y), fmaxf(r0.z, r0.w));
            float mnA = fminf(fminf(r0.x, r0.y), fminf(r0.z, r0.w));
            float mxB = fmaxf(fmaxf(r1.x, r1.y), fmaxf(r1.z, r1.w));
            float mnB = fminf(fminf(r1.x, r1.y), fminf(r1.z, r1.w));
            if (K == 32) {
#pragma unroll
                for (int off = 4; off > 0; off >>= 1) {
                    mxA = fmaxf(mxA, __shfl_xor_sync(0xffffffffu, mxA, off));
                    mnA = fminf(mnA, __shfl_xor_sync(0xffffffffu, mnA, off));
                    mxB = fmaxf(mxB, __shfl_xor_sync(0xffffffffu, mxB, off));
                    mnB = fminf(mnB, __shfl_xor_sync(0xffffffffu, mnB, off));
                }
                if ((tx & 7) == 0) {
                    int gA = (pblock >> 5) + (tx >> 3);
                    int gB = gA + 4;
                    pmax[(size_t)oc*GCOUNT + gA] = mxA;
                    pmin[(size_t)oc*GCOUNT + gA] = mnA;
                    pmax[(size_t)oc*GCOUNT + gB] = mxB;
                    pmin[(size_t)oc*GCOUNT + gB] = mnB;
                }
            } else { // K == 64
#pragma unroll
                for (int off = 8; off > 0; off >>= 1) {
                    mxA = fmaxf(mxA, __shfl_xor_sync(0xffffffffu, mxA, off));
                    mnA = fminf(mnA, __shfl_xor_sync(0xffffffffu, mnA, off));
                    mxB = fmaxf(mxB, __shfl_xor_sync(0xffffffffu, mxB, off));
                    mnB = fminf(mnB, __shfl_xor_sync(0xffffffffu, mnB, off));
                }
                if ((tx & 15) == 0) {
                    int gA = (pblock >> 6) + (tx >> 4);
                    int gB = gA + 2;
                    pmax[(size_t)oc*GCOUNT + gA] = mxA;
                    pmin[(size_t)oc*GCOUNT + gA] = mnA;
                    pmax[(size_t)oc*GCOUNT + gB] = mxB;
                    pmin[(size_t)oc*GCOUNT + gB] = mnB;
                }
            }
        }
    }
}

// ---------------- finalize BN: reduce partials -> (scale, shift) ----------------
__global__ __launch_bounds__(256) void finalize_kernel(const float* __restrict__ ps,
                                                       const float* __restrict__ ps2,
                                                       int nblk, float invP,
                                                       const float* __restrict__ gamma,
                                                       const float* __restrict__ beta,
                                                       float* __restrict__ s,
                                                       float* __restrict__ t)
{
    int c = blockIdx.x;
    float a = 0.0f, b = 0.0f;
    for (int i = threadIdx.x; i < nblk; i += 256) {
        a += ps [(size_t)c*nblk + i];
        b += ps2[(size_t)c*nblk + i];
    }
#pragma unroll
    for (int off = 16; off > 0; off >>= 1) {
        a += __shfl_down_sync(0xffffffffu, a, off);
        b += __shfl_down_sync(0xffffffffu, b, off);
    }
    __shared__ float sa[8], sb[8];
    int lane = threadIdx.x & 31, w = threadIdx.x >> 5;
    if (lane == 0) { sa[w] = a; sb[w] = b; }
    __syncthreads();
    if (threadIdx.x < 8) {
        a = sa[threadIdx.x]; b = sb[threadIdx.x];
#pragma unroll
        for (int off = 4; off > 0; off >>= 1) {
            a += __shfl_down_sync(0xffu, a, off);
            b += __shfl_down_sync(0xffu, b, off);
        }
        if (threadIdx.x == 0) {
            float mu  = a * invP;
            float var = b * invP - mu*mu;
            float rs  = 1.0f / sqrtf(var + 1e-5f);
            float sc  = gamma[c] * rs;
            s[c] = sc;
            t[c] = beta[c] - mu * sc;
        }
    }
}

// ---------------- apply BN to pooled max/min, write output ----------------
__global__ __launch_bounds__(256) void pool_apply_kernel(const float* __restrict__ pmax,
                                                         const float* __restrict__ pmin,
                                                         const float* __restrict__ s,
                                                         const float* __restrict__ t,
                                                         float* __restrict__ out,
                                                         int chbase)
{
    int gid = blockIdx.x*256 + threadIdx.x;   // 128 * 16384
    int oc = gid >> 14;
    int g  = gid & 16383;
    float sc = s[oc], tc = t[oc];
    float v  = (sc > 0.0f) ? pmax[gid] : pmin[gid];
    float r  = fmaxf(v*sc + tc, 0.0f);
    int b = g >> 10, m = g & 1023;
    out[OUT_OFS + ((size_t)(b*256 + chbase + oc))*MM + m] = r;
}

// ---------------- host launch sequence ----------------
extern "C" void kernel_launch(void* const* d_in, const int* in_sizes, int n_in,
                              void* d_out, int out_size)
{
    const float* pc   = (const float*)d_in[0];
    const float* feat = (const float*)d_in[1];
    const float *Wp[6], *bp[6], *gp[6], *bep[6];
    for (int i = 0; i < 6; i++) {
        Wp[i]  = (const float*)d_in[2 + 4*i];
        bp[i]  = (const float*)d_in[3 + 4*i];
        gp[i]  = (const float*)d_in[4 + 4*i];
        bep[i] = (const float*)d_in[5 + 4*i];
    }
    float* out = (float*)d_out;

    int *samp, *idx0, *idx1;
    float *bufA, *bufB, *ft, *sv, *tv, *ps, *ps2, *pmax, *pmin, *wt;
    cudaGetSymbolAddress((void**)&samp, g_samp);
    cudaGetSymbolAddress((void**)&idx0, g_idx0);
    cudaGetSymbolAddress((void**)&idx1, g_idx1);
    cudaGetSymbolAddress((void**)&bufA, g_bufA);
    cudaGetSymbolAddress((void**)&bufB, g_bufB);
    cudaGetSymbolAddress((void**)&ft,   g_ft);
    cudaGetSymbolAddress((void**)&sv,   g_s);
    cudaGetSymbolAddress((void**)&tv,   g_t);
    cudaGetSymbolAddress((void**)&ps,   g_ps);
    cudaGetSymbolAddress((void**)&ps2,  g_ps2);
    cudaGetSymbolAddress((void**)&pmax, g_pmax);
    cudaGetSymbolAddress((void**)&pmin, g_pmin);
    cudaGetSymbolAddress((void**)&wt,   g_wt);

    const float r2_0 = (float)(0.1*0.1);
    const float r2_1 = (float)(0.2*0.2);

    WPtrs wargs;
    for (int l = 0; l < 6; l++) wargs.w[l] = Wp[l];
    wtr_kernel<<<6, 256>>>(wargs, wt);
    ftr_kernel<<<dim3(128, 2, BB), dim3(32, 8)>>>(feat, ft);
    fps_kernel<<<BB, 512>>>(pc, samp, out);
    ballquery_kernel<<<dim3(BB,16), 256, 3*NN*sizeof(float)>>>(pc, samp, idx0, r2_0, K0);
    ballquery_kernel<<<dim3(BB,16), 256, 3*NN*sizeof(float)>>>(pc, samp, idx1, r2_1, K1);

    dim3 tb(32, 8);
    const int nbx0 = P0/256, nbx1 = P1/256;

    // -------- branch 0 (K=32): 67 -> 64 -> 64 -> 128 --------
    conv_kernel<true,false><<<dim3(nbx0, 2), tb>>>(nullptr, wt + 0*12288, bp[0], nullptr, nullptr,
        bufA, ps, ps2, nullptr, nullptr, 67, 5, 64, P0, K0, pc, ft, out, idx0, 15, 5);
    finalize_kernel<<<64, 256>>>(ps, ps2, nbx0, 1.0f/(float)P0, gp[0], bep[0], sv, tv);
    conv_kernel<false,false><<<dim3(nbx0, 2), tb>>>(bufA, wt + 1*12288, bp[1], sv, tv,
        bufB, ps, ps2, nullptr, nullptr, 64, 4, 64, P0, K0, nullptr, nullptr, nullptr, nullptr, 0, 0);
    finalize_kernel<<<64, 256>>>(ps, ps2, nbx0, 1.0f/(float)P0, gp[1], bep[1], sv, tv);
    conv_kernel<false,true><<<dim3(nbx0, 4), tb>>>(bufB, wt + 2*12288, bp[2], sv, tv,
        nullptr, ps, ps2, pmax, pmin, 64, 4, 128, P0, K0, nullptr, nullptr, nullptr, nullptr, 0, 0);
    finalize_kernel<<<128, 256>>>(ps, ps2, nbx0, 1.0f/(float)P0, gp[2], bep[2], sv, tv);
    pool_apply_kernel<<<(128*GCOUNT)/256, 256>>>(pmax, pmin, sv, tv, out, 0);

    // -------- branch 1 (K=64): 67 -> 64 -> 96 -> 128 --------
    conv_kernel<true,false><<<dim3(nbx1, 2), tb>>>(nullptr, wt + 3*12288, bp[3], nullptr, nullptr,
        bufA, ps, ps2, nullptr, nullptr, 67, 5, 64, P1, K1, pc, ft, out, idx1, 16, 6);
    finalize_kernel<<<64, 256>>>(ps, ps2, nbx1, 1.0f/(float)P1, gp[3], bep[3], sv, tv);
    conv_kernel<false,false><<<dim3(nbx1, 3), tb>>>(bufA, wt + 4*12288, bp[4], sv, tv,
        bufB, ps, ps2, nullptr, nullptr, 64, 4, 96, P1, K1, nullptr, nullptr, nullptr, nullptr, 0, 0);
    finalize_kernel<<<96, 256>>>(ps, ps2, nbx1, 1.0f/(float)P1, gp[4], bep[4], sv, tv);
    conv_kernel<false,true><<<dim3(nbx1, 4), tb>>>(bufB, wt + 5*12288, bp[5], sv, tv,
        nullptr, ps, ps2, pmax, pmin, 96, 6, 128, P1, K1, nullptr, nullptr, nullptr, nullptr, 0, 0);
    finalize_kernel<<<128, 256>>>(ps, ps2, nbx1, 1.0f/(float)P1, gp[5], bep[5], sv, tv);
    pool_apply_kernel<<<(128*GCOUNT)/256, 256>>>(pmax, pmin, sv, tv, out, 128);
}

// round 4
// speedup vs baseline: 3.0444x; 1.2478x over previous
#include <cuda_runtime.h>
#include <cstdint>

#define BB 16
#define NN 4096
#define MM 1024
#define K0 32
#define K1 64
#define P0 (BB*MM*K0)     // 524288
#define P1 (BB*MM*K1)     // 1048576
#define OUT_OFS (BB*3*MM) // 49152
#define GCOUNT (BB*MM)    // 16384 pool groups per channel

#define FMA2(acc, x, w) asm("fma.rn.f32x2 %0, %1, %2, %0;" : "+l"(acc) : "l"(x), "l"(w))
#define PACK2(dst, f)   asm("mov.b64 %0, {%1, %1};" : "=l"(dst) : "r"(__float_as_uint(f)))

__device__ __forceinline__ float2 unpk(unsigned long long v) {
    return make_float2(__uint_as_float((unsigned)v), __uint_as_float((unsigned)(v >> 32)));
}

// ---------------- scratch (device globals; no allocation allowed) ----------------
__device__ int   g_samp[BB*MM];
__device__ int   g_idx0[P0];
__device__ int   g_idx1[P1];
__device__ float g_bufA[64*P1];    // 256 MB
__device__ float g_bufB[96*P1];    // 384 MB
__device__ float g_ft[BB*NN*64];   // transposed features (B,N,64)
__device__ float g_s[128];
__device__ float g_t[128];
__device__ float g_ps [128*4096];
__device__ float g_ps2[128*4096];
__device__ float g_pmax[128*GCOUNT];
__device__ float g_pmin[128*GCOUNT];
__device__ float g_wt [6*12288];

struct WPtrs { const float* w[6]; };

// ---------------- combined weight transpose + channel permute ----------------
__global__ void wtr_kernel(WPtrs wp, float* __restrict__ wt)
{
    const int cins[6]  = {67, 64, 64, 67, 64, 96};
    const int cpads[6] = {80, 64, 64, 80, 64, 96};
    const int couts[6] = {64, 64, 128, 64, 96, 128};
    const int gat[6]   = {1, 0, 0, 1, 0, 0};
    int l = blockIdx.x;
    const float* W = wp.w[l];
    int cin = cins[l], cpad = cpads[l], cout = couts[l];
    float* dst = wt + l*12288;
    int total = cpad * cout;
    for (int e = threadIdx.x; e < total; e += 256) {
        int c = e / cout, o = e - c*cout;
        int src;
        if (gat[l]) src = (c < 64) ? c + 3 : (c < 67 ? c - 64 : -1);
        else        src = (c < cin) ? c : -1;
        dst[e] = (src >= 0) ? W[o*cin + src] : 0.0f;
    }
}

// ---------------- feature transpose: (B,64,N) -> (B,N,64) ----------------
__global__ __launch_bounds__(256) void ftr_kernel(const float* __restrict__ feat,
                                                  float* __restrict__ ft)
{
    __shared__ float tile[32][33];
    int b = blockIdx.z, c0 = blockIdx.y*32, n0 = blockIdx.x*32;
    int tx = threadIdx.x, ty = threadIdx.y;
#pragma unroll
    for (int k = 0; k < 4; k++) {
        int c = c0 + ty + k*8;
        tile[ty + k*8][tx] = feat[(size_t)(b*64 + c)*NN + n0 + tx];
    }
    __syncthreads();
#pragma unroll
    for (int k = 0; k < 4; k++) {
        int n = n0 + ty + k*8;
        ft[((size_t)b*NN + n)*64 + c0 + tx] = tile[tx][ty + k*8];
    }
}

// ---------------- FPS: one block per batch; REDUX-based argmax ----------------
__global__ __launch_bounds__(512) void fps_kernel(const float* __restrict__ pc,
                                                  int* __restrict__ samp,
                                                  float* __restrict__ dout)
{
    int b   = blockIdx.x;
    int tid = threadIdx.x;
    const float* px = pc + (size_t)b*3*NN;
    const float* py = px + NN;
    const float* pz = py + NN;

    float x[8], yv[8], z[8], dmin[8];
#pragma unroll
    for (int j = 0; j < 8; j++) {
        int i = tid + j*512;
        x[j] = px[i]; yv[j] = py[i]; z[j] = pz[i];
        dmin[j] = 1e10f;
    }

    __shared__ unsigned svu[16];
    __shared__ unsigned siu[16];
    __shared__ int sfar;

    int lane = tid & 31, w = tid >> 5;
    int far = 0;
    for (int it = 0; it < MM; it++) {
        if (tid == 0) {
            samp[b*MM + it] = far;
            dout[(b*3+0)*MM + it] = px[far];
            dout[(b*3+1)*MM + it] = py[far];
            dout[(b*3+2)*MM + it] = pz[far];
        }
        float cx = px[far], cy = py[far], cz = pz[far];

        float bv = -1.0f; int bi = 0;
#pragma unroll
        for (int j = 0; j < 8; j++) {
            float dx = x[j]  - cx;
            float dy = yv[j] - cy;
            float dz = z[j]  - cz;
            float d = __fadd_rn(__fadd_rn(__fmul_rn(dx,dx), __fmul_rn(dy,dy)), __fmul_rn(dz,dz));
            float nd = fminf(dmin[j], d);
            dmin[j] = nd;
            if (nd > bv) { bv = nd; bi = tid + j*512; }
        }
        // warp argmax via REDUX (positive floats: bit order == value order)
        unsigned fb = __float_as_uint(bv);
        unsigned mw = __reduce_max_sync(0xffffffffu, fb);
        unsigned ci = (fb == mw) ? (unsigned)bi : 0xffffffffu;
        unsigned mi = __reduce_min_sync(0xffffffffu, ci);
        if (lane == 0) { svu[w] = mw; siu[w] = mi; }
        __syncthreads();
        if (w == 0) {
            unsigned f2 = (tid < 16) ? svu[tid] : 0u;
            unsigned i2 = (tid < 16) ? siu[tid] : 0xffffffffu;
            unsigned m2 = __reduce_max_sync(0xffffffffu, f2);
            unsigned c2 = (f2 == m2) ? i2 : 0xffffffffu;
            unsigned r2 = __reduce_min_sync(0xffffffffu, c2);
            if (tid == 0) sfar = (int)r2;
        }
        __syncthreads();
        far = sfar;
    }
}

// ---------------- Fused dual-radius ball query: one scan, both K lists ----------------
__global__ __launch_bounds__(256) void ballquery2_kernel(const float* __restrict__ pc,
                                                         const int* __restrict__ samp,
                                                         int* __restrict__ gidx0,
                                                         int* __restrict__ gidx1,
                                                         float r2a, float r2b)
{
    extern __shared__ float sh[];
    float* sx = sh;
    float* sy = sh + NN;
    float* sz = sh + 2*NN;

    int b = blockIdx.x;
    const float* px = pc + (size_t)b*3*NN;
    for (int i = threadIdx.x; i < NN; i += blockDim.x) {
        sx[i] = px[i]; sy[i] = px[NN + i]; sz[i] = px[2*NN + i];
    }
    __syncthreads();

    int lane = threadIdx.x & 31;
    int wid  = threadIdx.x >> 5;
    int mstart = blockIdx.y * 64;
    unsigned lt = (1u << lane) - 1u;

    for (int m = mstart + wid; m < mstart + 64; m += 8) {
        int ci = samp[b*MM + m];
        float cx = sx[ci], cy = sy[ci], cz = sz[ci];
        int cnt0 = 0, cnt1 = 0, f0 = -1, f1 = -1;
        int* out0 = gidx0 + ((size_t)(b*MM + m))*K0;
        int* out1 = gidx1 + ((size_t)(b*MM + m))*K1;

        for (int base = 0; base < NN && (cnt0 < K0 || cnt1 < K1); base += 32) {
            int i = base + lane;
            float dx = sx[i] - cx;
            float dy = sy[i] - cy;
            float dz = sz[i] - cz;
            float d = __fadd_rn(__fadd_rn(__fmul_rn(dx,dx), __fmul_rn(dy,dy)), __fmul_rn(dz,dz));
            bool ok0 = d < r2a;
            bool ok1 = d < r2b;
            unsigned m0 = __ballot_sync(0xffffffffu, ok0);
            unsigned m1 = __ballot_sync(0xffffffffu, ok1);
            if (f0 < 0 && m0) f0 = base + __ffs(m0) - 1;
            if (f1 < 0 && m1) f1 = base + __ffs(m1) - 1;
            int p0 = cnt0 + __popc(m0 & lt);
            int p1 = cnt1 + __popc(m1 & lt);
            if (ok0 && p0 < K0) out0[p0] = i;
            if (ok1 && p1 < K1) out1[p1] = i;
            cnt0 = min(K0, cnt0 + __popc(m0));
            cnt1 = min(K1, cnt1 + __popc(m1));
        }
        for (int p = cnt0 + lane; p < K0; p += 32) out0[p] = f0;
        for (int p = cnt1 + lane; p < K1; p += 32) out1[p] = f1;
    }
}

// ---------------- Tiled GEMM: 32 out x 256 pos, double buffered, FFMA2 core ----------------
template<bool GATHER, bool POOL>
__global__ __launch_bounds__(256) void conv_kernel(
    const float* __restrict__ xin, const float* __restrict__ Wt,
    const float* __restrict__ bias,
    const float* __restrict__ bns, const float* __restrict__ bnt,
    float* __restrict__ y, float* __restrict__ ps, float* __restrict__ ps2,
    float* __restrict__ pmax, float* __restrict__ pmin,
    int cin, int nk, int cout, int P, int K,
    const float* __restrict__ pc, const float* __restrict__ ft,
    const float* __restrict__ newpc, const int* __restrict__ gidx,
    int mkshift, int kshift)
{
    __shared__ __align__(16) float xs[2][16][256];
    __shared__ __align__(16) float ws[2][16][32];
    __shared__ float ssA[96], stA[96];
    __shared__ int sidx[256];

    const int tx = threadIdx.x, ty = threadIdx.y;
    const int t  = ty*32 + tx;
    const int pblock = blockIdx.x * 256;
    const int oblock = blockIdx.y * 32;
    const int nblk = gridDim.x;

    if (GATHER) {
        sidx[t] = gidx[pblock + t];
    } else {
        if (t < cin) { ssA[t] = bns[t]; stA[t] = bnt[t]; }
    }
    __syncthreads();

    int g_bb = 0, g_mm = 0, g_ix = 0;
    size_t g_fb = 0;
    if (GATHER) {
        int p = pblock + t;
        g_bb = p >> mkshift;
        g_mm = (p >> kshift) & (MM - 1);
        g_ix = sidx[t];
        g_fb = ((size_t)g_bb*NN + g_ix)*64;
    }

    float4 xr[4];
    float  gxr[16];
    float4 wr = make_float4(0,0,0,0);

    auto load_x = [&](int kc) {
        if (GATHER) {
            if (kc < 4) {
#pragma unroll
                for (int j = 0; j < 4; j++) {
                    float4 v = *(const float4*)&ft[g_fb + kc*16 + j*4];
                    gxr[j*4+0] = v.x; gxr[j*4+1] = v.y; gxr[j*4+2] = v.z; gxr[j*4+3] = v.w;
                }
            } else {
#pragma unroll
                for (int i = 0; i < 16; i++) gxr[i] = 0.0f;
#pragma unroll
                for (int d = 0; d < 3; d++)
                    gxr[d] = pc[(size_t)(g_bb*3 + d)*NN + g_ix] - newpc[(size_t)(g_bb*3 + d)*MM + g_mm];
            }
        } else {
            int c0 = kc * 16;
#pragma unroll
            for (int i = 0; i < 4; i++) {
                int f  = t + i*256;
                int cc = f >> 6, q = f & 63;
                int c  = c0 + cc;
                float4 v = *(const float4*)&xin[(size_t)c*P + pblock + q*4];
                float sc = ssA[c], tc = stA[c];
                v.x = fmaxf(v.x*sc + tc, 0.0f);
                v.y = fmaxf(v.y*sc + tc, 0.0f);
                v.z = fmaxf(v.z*sc + tc, 0.0f);
                v.w = fmaxf(v.w*sc + tc, 0.0f);
                xr[i] = v;
            }
        }
    };
    auto load_w = [&](int kc) {
        if (t < 128) {
            int cc = t >> 3, o4 = t & 7;
            wr = *(const float4*)&Wt[(size_t)(kc*16 + cc)*cout + oblock + o4*4];
        }
    };
    auto store_stage = [&](int buf) {
        if (GATHER) {
#pragma unroll
            for (int i = 0; i < 16; i++) xs[buf][i][t] = gxr[i];
        } else {
#pragma unroll
            for (int i = 0; i < 4; i++) {
                int f  = t + i*256;
                int cc = f >> 6, q = f & 63;
                *(float4*)&xs[buf][cc][q*4] = xr[i];
            }
        }
        if (t < 128) {
            int cc = t >> 3, o4 = t & 7;
            *(float4*)&ws[buf][cc][o4*4] = wr;
        }
    };

    unsigned long long acc[4][4];
#pragma unroll
    for (int o = 0; o < 4; o++)
#pragma unroll
        for (int p = 0; p < 4; p++) acc[o][p] = 0ULL;

    load_x(0); load_w(0); store_stage(0);
    __syncthreads();

    for (int kc = 0; kc < nk; kc++) {
        int buf = kc & 1;
        if (kc + 1 < nk) { load_x(kc + 1); load_w(kc + 1); }
#pragma unroll
        for (int cc = 0; cc < 16; cc++) {
            float4 wv = *(const float4*)&ws[buf][cc][ty*4];
            ulonglong2 a01 = *(const ulonglong2*)&xs[buf][cc][tx*4];
            ulonglong2 b01 = *(const ulonglong2*)&xs[buf][cc][128 + tx*4];
            unsigned long long wo0, wo1, wo2, wo3;
            PACK2(wo0, wv.x); PACK2(wo1, wv.y); PACK2(wo2, wv.z); PACK2(wo3, wv.w);
            FMA2(acc[0][0], a01.x, wo0); FMA2(acc[0][1], a01.y, wo0);
            FMA2(acc[0][2], b01.x, wo0); FMA2(acc[0][3], b01.y, wo0);
            FMA2(acc[1][0], a01.x, wo1); FMA2(acc[1][1], a01.y, wo1);
            FMA2(acc[1][2], b01.x, wo1); FMA2(acc[1][3], b01.y, wo1);
            FMA2(acc[2][0], a01.x, wo2); FMA2(acc[2][1], a01.y, wo2);
            FMA2(acc[2][2], b01.x, wo2); FMA2(acc[2][3], b01.y, wo2);
            FMA2(acc[3][0], a01.x, wo3); FMA2(acc[3][1], a01.y, wo3);
            FMA2(acc[3][2], b01.x, wo3); FMA2(acc[3][3], b01.y, wo3);
        }
        if (kc + 1 < nk) store_stage(buf ^ 1);
        __syncthreads();
    }

    int pbase0 = pblock + tx*4;
#pragma unroll
    for (int o = 0; o < 4; o++) {
        int oc = oblock + ty*4 + o;
        float bv = bias[oc];
        float2 u0 = unpk(acc[o][0]);
        float2 u1 = unpk(acc[o][1]);
        float2 u2 = unpk(acc[o][2]);
        float2 u3 = unpk(acc[o][3]);
        float4 r0 = make_float4(u0.x+bv, u0.y+bv, u1.x+bv, u1.y+bv);
        float4 r1 = make_float4(u2.x+bv, u2.y+bv, u3.x+bv, u3.y+bv);
        if (!POOL) {
            *(float4*)&y[(size_t)oc*P + pbase0]       = r0;
            *(float4*)&y[(size_t)oc*P + pbase0 + 128] = r1;
        }
        float s1 = ((r0.x+r0.y)+(r0.z+r0.w)) + ((r1.x+r1.y)+(r1.z+r1.w));
        float s2 = (r0.x*r0.x + r0.y*r0.y + r0.z*r0.z + r0.w*r0.w)
                 + (r1.x*r1.x + r1.y*r1.y + r1.z*r1.z + r1.w*r1.w);
#pragma unroll
        for (int off = 16; off > 0; off >>= 1) {
            s1 += __shfl_down_sync(0xffffffffu, s1, off);
            s2 += __shfl_down_sync(0xffffffffu, s2, off);
        }
        if (tx == 0) {
            ps [(size_t)oc*nblk + blockIdx.x] = s1;
            ps2[(size_t)oc*nblk + blockIdx.x] = s2;
        }
        if (POOL) {
            float mxA = fmaxf(fmaxf(r0.x, r0.y), fmaxf(r0.z, r0.w));
            float mnA = fminf(fminf(r0.x, r0.y), fminf(r0.z, r0.w));
            float mxB = fmaxf(fmaxf(r1.x, r1.y), fmaxf(r1.z, r1.w));
            float mnB = fminf(fminf(r1.x, r1.y), fminf(r1.z, r1.w));
            if (K == 32) {
#pragma unroll
                for (int off = 4; off > 0; off >>= 1) {
                    mxA = fmaxf(mxA, __shfl_xor_sync(0xffffffffu, mxA, off));
                    mnA = fminf(mnA, __shfl_xor_sync(0xffffffffu, mnA, off));
                    mxB = fmaxf(mxB, __shfl_xor_sync(0xffffffffu, mxB, off));
                    mnB = fminf(mnB, __shfl_xor_sync(0xffffffffu, mnB, off));
                }
                if ((tx & 7) == 0) {
                    int gA = (pblock >> 5) + (tx >> 3);
                    int gB = gA + 4;
                    pmax[(size_t)oc*GCOUNT + gA] = mxA;
                    pmin[(size_t)oc*GCOUNT + gA] = mnA;
                    pmax[(size_t)oc*GCOUNT + gB] = mxB;
                    pmin[(size_t)oc*GCOUNT + gB] = mnB;
                }
            } else { // K == 64
#pragma unroll
                for (int off = 8; off > 0; off >>= 1) {
                    mxA = fmaxf(mxA, __shfl_xor_sync(0xffffffffu, mxA, off));
                    mnA = fminf(mnA, __shfl_xor_sync(0xffffffffu, mnA, off));
                    mxB = fmaxf(mxB, __shfl_xor_sync(0xffffffffu, mxB, off));
                    mnB = fminf(mnB, __shfl_xor_sync(0xffffffffu, mnB, off));
                }
                if ((tx & 15) == 0) {
                    int gA = (pblock >> 6) + (tx >> 4);
                    int gB = gA + 2;
                    pmax[(size_t)oc*GCOUNT + gA] = mxA;
                    pmin[(size_t)oc*GCOUNT + gA] = mnA;
                    pmax[(size_t)oc*GCOUNT + gB] = mxB;
                    pmin[(size_t)oc*GCOUNT + gB] = mnB;
                }
            }
        }
    }
}

// ---------------- finalize BN: reduce partials -> (scale, shift) ----------------
__global__ __launch_bounds__(256) void finalize_kernel(const float* __restrict__ ps,
                                                       const float* __restrict__ ps2,
                                                       int nblk, float invP,
                                                       const float* __restrict__ gamma,
                                                       const float* __restrict__ beta,
                                                       float* __restrict__ s,
                                                       float* __restrict__ t)
{
    int c = blockIdx.x;
    float a = 0.0f, b = 0.0f;
    for (int i = threadIdx.x; i < nblk; i += 256) {
        a += ps [(size_t)c*nblk + i];
        b += ps2[(size_t)c*nblk + i];
    }
#pragma unroll
    for (int off = 16; off > 0; off >>= 1) {
        a += __shfl_down_sync(0xffffffffu, a, off);
        b += __shfl_down_sync(0xffffffffu, b, off);
    }
    __shared__ float sa[8], sb[8];
    int lane = threadIdx.x & 31, w = threadIdx.x >> 5;
    if (lane == 0) { sa[w] = a; sb[w] = b; }
    __syncthreads();
    if (threadIdx.x < 8) {
        a = sa[threadIdx.x]; b = sb[threadIdx.x];
#pragma unroll
        for (int off = 4; off > 0; off >>= 1) {
            a += __shfl_down_sync(0xffu, a, off);
            b += __shfl_down_sync(0xffu, b, off);
        }
        if (threadIdx.x == 0) {
            float mu  = a * invP;
            float var = b * invP - mu*mu;
            float rs  = 1.0f / sqrtf(var + 1e-5f);
            float sc  = gamma[c] * rs;
            s[c] = sc;
            t[c] = beta[c] - mu * sc;
        }
    }
}

// ---------------- apply BN to pooled max/min, write output ----------------
__global__ __launch_bounds__(256) void pool_apply_kernel(const float* __restrict__ pmax,
                                                         const float* __restrict__ pmin,
                                                         const float* __restrict__ s,
                                                         const float* __restrict__ t,
                                                         float* __restrict__ out,
                                                         int chbase)
{
    int gid = blockIdx.x*256 + threadIdx.x;
    int oc = gid >> 14;
    int g  = gid & 16383;
    float sc = s[oc], tc = t[oc];
    float v  = (sc > 0.0f) ? pmax[gid] : pmin[gid];
    float r  = fmaxf(v*sc + tc, 0.0f);
    int b = g >> 10, m = g & 1023;
    out[OUT_OFS + ((size_t)(b*256 + chbase + oc))*MM + m] = r;
}

// ---------------- host launch sequence ----------------
extern "C" void kernel_launch(void* const* d_in, const int* in_sizes, int n_in,
                              void* d_out, int out_size)
{
    const float* pc   = (const float*)d_in[0];
    const float* feat = (const float*)d_in[1];
    const float *Wp[6], *bp[6], *gp[6], *bep[6];
    for (int i = 0; i < 6; i++) {
        Wp[i]  = (const float*)d_in[2 + 4*i];
        bp[i]  = (const float*)d_in[3 + 4*i];
        gp[i]  = (const float*)d_in[4 + 4*i];
        bep[i] = (const float*)d_in[5 + 4*i];
    }
    float* out = (float*)d_out;

    int *samp, *idx0, *idx1;
    float *bufA, *bufB, *ft, *sv, *tv, *ps, *ps2, *pmax, *pmin, *wt;
    cudaGetSymbolAddress((void**)&samp, g_samp);
    cudaGetSymbolAddress((void**)&idx0, g_idx0);
    cudaGetSymbolAddress((void**)&idx1, g_idx1);
    cudaGetSymbolAddress((void**)&bufA, g_bufA);
    cudaGetSymbolAddress((void**)&bufB, g_bufB);
    cudaGetSymbolAddress((void**)&ft,   g_ft);
    cudaGetSymbolAddress((void**)&sv,   g_s);
    cudaGetSymbolAddress((void**)&tv,   g_t);
    cudaGetSymbolAddress((void**)&ps,   g_ps);
    cudaGetSymbolAddress((void**)&ps2,  g_ps2);
    cudaGetSymbolAddress((void**)&pmax, g_pmax);
    cudaGetSymbolAddress((void**)&pmin, g_pmin);
    cudaGetSymbolAddress((void**)&wt,   g_wt);

    const float r2_0 = (float)(0.1*0.1);
    const float r2_1 = (float)(0.2*0.2);

    WPtrs wargs;
    for (int l = 0; l < 6; l++) wargs.w[l] = Wp[l];
    wtr_kernel<<<6, 256>>>(wargs, wt);
    ftr_kernel<<<dim3(128, 2, BB), dim3(32, 8)>>>(feat, ft);
    fps_kernel<<<BB, 512>>>(pc, samp, out);
    ballquery2_kernel<<<dim3(BB,16), 256, 3*NN*sizeof(float)>>>(pc, samp, idx0, idx1, r2_0, r2_1);

    dim3 tb(32, 8);
    const int nbx0 = P0/256, nbx1 = P1/256;

    // -------- branch 0 (K=32): 67 -> 64 -> 64 -> 128 --------
    conv_kernel<true,false><<<dim3(nbx0, 2), tb>>>(nullptr, wt + 0*12288, bp[0], nullptr, nullptr,
        bufA, ps, ps2, nullptr, nullptr, 67, 5, 64, P0, K0, pc, ft, out, idx0, 15, 5);
    finalize_kernel<<<64, 256>>>(ps, ps2, nbx0, 1.0f/(float)P0, gp[0], bep[0], sv, tv);
    conv_kernel<false,false><<<dim3(nbx0, 2), tb>>>(bufA, wt + 1*12288, bp[1], sv, tv,
        bufB, ps, ps2, nullptr, nullptr, 64, 4, 64, P0, K0, nullptr, nullptr, nullptr, nullptr, 0, 0);
    finalize_kernel<<<64, 256>>>(ps, ps2, nbx0, 1.0f/(float)P0, gp[1], bep[1], sv, tv);
    conv_kernel<false,true><<<dim3(nbx0, 4), tb>>>(bufB, wt + 2*12288, bp[2], sv, tv,
        nullptr, ps, ps2, pmax, pmin, 64, 4, 128, P0, K0, nullptr, nullptr, nullptr, nullptr, 0, 0);
    finalize_kernel<<<128, 256>>>(ps, ps2, nbx0, 1.0f/(float)P0, gp[2], bep[2], sv, tv);
    pool_apply_kernel<<<(128*GCOUNT)/256, 256>>>(pmax, pmin, sv, tv, out, 0);

    // -------- branch 1 (K=64): 67 -> 64 -> 96 -> 128 --------
    conv_kernel<true,false><<<dim3(nbx1, 2), tb>>>(nullptr, wt + 3*12288, bp[3], nullptr, nullptr,
        bufA, ps, ps2, nullptr, nullptr, 67, 5, 64, P1, K1, pc, ft, out, idx1, 16, 6);
    finalize_kernel<<<64, 256>>>(ps, ps2, nbx1, 1.0f/(float)P1, gp[3], bep[3], sv, tv);
    conv_kernel<false,false><<<dim3(nbx1, 3), tb>>>(bufA, wt + 4*12288, bp[4], sv, tv,
        bufB, ps, ps2, nullptr, nullptr, 64, 4, 96, P1, K1, nullptr, nullptr, nullptr, nullptr, 0, 0);
    finalize_kernel<<<96, 256>>>(ps, ps2, nbx1, 1.0f/(float)P1, gp[4], bep[4], sv, tv);
    conv_kernel<false,true><<<dim3(nbx1, 4), tb>>>(bufB, wt + 5*12288, bp[5], sv, tv,
        nullptr, ps, ps2, pmax, pmin, 96, 6, 128, P1, K1, nullptr, nullptr, nullptr, nullptr, 0, 0);
    finalize_kernel<<<128, 256>>>(ps, ps2, nbx1, 1.0f/(float)P1, gp[5], bep[5], sv, tv);
    pool_apply_kernel<<<(128*GCOUNT)/256, 256>>>(pmax, pmin, sv, tv, out, 128);
}

// round 5
// speedup vs baseline: 3.4556x; 1.1351x over previous
#include <cuda_runtime.h>
#include <cstdint>

#define BB 16
#define NN 4096
#define MM 1024
#define K0 32
#define K1 64
#define P0 (BB*MM*K0)     // 524288
#define P1 (BB*MM*K1)     // 1048576
#define OUT_OFS (BB*3*MM) // 49152
#define GCOUNT (BB*MM)    // 16384 pool groups per channel

#define FMA2(acc, x, w) asm("fma.rn.f32x2 %0, %1, %2, %0;" : "+l"(acc) : "l"(x), "l"(w))
#define PACK2(dst, f)   asm("mov.b64 %0, {%1, %1};" : "=l"(dst) : "r"(__float_as_uint(f)))

__device__ __forceinline__ float2 unpk(unsigned long long v) {
    return make_float2(__uint_as_float((unsigned)v), __uint_as_float((unsigned)(v >> 32)));
}

// ---------------- scratch (device globals; no allocation allowed) ----------------
__device__ int   g_samp[BB*MM];
__device__ int   g_idx0[P0];
__device__ int   g_idx1[P1];
__device__ float g_bufA[64*P1];    // 256 MB
__device__ float g_bufB[96*P1];    // 384 MB
__device__ float g_ft[BB*NN*64];   // transposed features (B,N,64)
__device__ float g_s[128];
__device__ float g_t[128];
__device__ float g_ps [128*4096];
__device__ float g_ps2[128*4096];
__device__ float g_pmax[128*GCOUNT];
__device__ float g_pmin[128*GCOUNT];
__device__ float g_wt [6*12288];

struct WPtrs { const float* w[6]; };

// ---------------- combined weight transpose + channel permute + out-pad ----------------
__global__ void wtr_kernel(WPtrs wp, float* __restrict__ wt)
{
    const int cins[6]   = {67, 64, 64, 67, 64, 96};
    const int cpads[6]  = {80, 64, 64, 80, 64, 96};
    const int couts[6]  = {64, 64, 128, 64, 96, 128};
    const int copads[6] = {64, 64, 128, 64, 128, 128};
    const int gat[6]    = {1, 0, 0, 1, 0, 0};
    int l = blockIdx.x;
    const float* W = wp.w[l];
    int cin = cins[l], cpad = cpads[l], cout = couts[l], copad = copads[l];
    float* dst = wt + l*12288;
    int total = cpad * copad;
    for (int e = threadIdx.x; e < total; e += 256) {
        int c = e / copad, o = e - c*copad;
        int src;
        if (gat[l]) src = (c < 64) ? c + 3 : (c < 67 ? c - 64 : -1);
        else        src = (c < cin) ? c : -1;
        dst[e] = (src >= 0 && o < cout) ? W[o*cin + src] : 0.0f;
    }
}

// ---------------- feature transpose: (B,64,N) -> (B,N,64) ----------------
__global__ __launch_bounds__(256) void ftr_kernel(const float* __restrict__ feat,
                                                  float* __restrict__ ft)
{
    __shared__ float tile[32][33];
    int b = blockIdx.z, c0 = blockIdx.y*32, n0 = blockIdx.x*32;
    int tx = threadIdx.x, ty = threadIdx.y;
#pragma unroll
    for (int k = 0; k < 4; k++) {
        int c = c0 + ty + k*8;
        tile[ty + k*8][tx] = feat[(size_t)(b*64 + c)*NN + n0 + tx];
    }
    __syncthreads();
#pragma unroll
    for (int k = 0; k < 4; k++) {
        int n = n0 + ty + k*8;
        ft[((size_t)b*NN + n)*64 + c0 + tx] = tile[tx][ty + k*8];
    }
}

// ---------------- FPS: one block per batch; REDUX-based argmax ----------------
__global__ __launch_bounds__(512) void fps_kernel(const float* __restrict__ pc,
                                                  int* __restrict__ samp,
                                                  float* __restrict__ dout)
{
    int b   = blockIdx.x;
    int tid = threadIdx.x;
    const float* px = pc + (size_t)b*3*NN;
    const float* py = px + NN;
    const float* pz = py + NN;

    float x[8], yv[8], z[8], dmin[8];
#pragma unroll
    for (int j = 0; j < 8; j++) {
        int i = tid + j*512;
        x[j] = px[i]; yv[j] = py[i]; z[j] = pz[i];
        dmin[j] = 1e10f;
    }

    __shared__ unsigned svu[16];
    __shared__ unsigned siu[16];
    __shared__ int sfar;

    int lane = tid & 31, w = tid >> 5;
    int far = 0;
    for (int it = 0; it < MM; it++) {
        if (tid == 0) {
            samp[b*MM + it] = far;
            dout[(b*3+0)*MM + it] = px[far];
            dout[(b*3+1)*MM + it] = py[far];
            dout[(b*3+2)*MM + it] = pz[far];
        }
        float cx = px[far], cy = py[far], cz = pz[far];

        float bv = -1.0f; int bi = 0;
#pragma unroll
        for (int j = 0; j < 8; j++) {
            float dx = x[j]  - cx;
            float dy = yv[j] - cy;
            float dz = z[j]  - cz;
            float d = __fadd_rn(__fadd_rn(__fmul_rn(dx,dx), __fmul_rn(dy,dy)), __fmul_rn(dz,dz));
            float nd = fminf(dmin[j], d);
            dmin[j] = nd;
            if (nd > bv) { bv = nd; bi = tid + j*512; }
        }
        unsigned fb = __float_as_uint(bv);
        unsigned mw = __reduce_max_sync(0xffffffffu, fb);
        unsigned ci = (fb == mw) ? (unsigned)bi : 0xffffffffu;
        unsigned mi = __reduce_min_sync(0xffffffffu, ci);
        if (lane == 0) { svu[w] = mw; siu[w] = mi; }
        __syncthreads();
        if (w == 0) {
            unsigned f2 = (tid < 16) ? svu[tid] : 0u;
            unsigned i2 = (tid < 16) ? siu[tid] : 0xffffffffu;
            unsigned m2 = __reduce_max_sync(0xffffffffu, f2);
            unsigned c2 = (f2 == m2) ? i2 : 0xffffffffu;
            unsigned r2 = __reduce_min_sync(0xffffffffu, c2);
            if (tid == 0) sfar = (int)r2;
        }
        __syncthreads();
        far = sfar;
    }
}

// ---------------- Fused dual-radius ball query: one scan, both K lists ----------------
__global__ __launch_bounds__(256) void ballquery2_kernel(const float* __restrict__ pc,
                                                         const int* __restrict__ samp,
                                                         int* __restrict__ gidx0,
                                                         int* __restrict__ gidx1,
                                                         float r2a, float r2b)
{
    extern __shared__ float sh[];
    float* sx = sh;
    float* sy = sh + NN;
    float* sz = sh + 2*NN;

    int b = blockIdx.x;
    const float* px = pc + (size_t)b*3*NN;
    for (int i = threadIdx.x; i < NN; i += blockDim.x) {
        sx[i] = px[i]; sy[i] = px[NN + i]; sz[i] = px[2*NN + i];
    }
    __syncthreads();

    int lane = threadIdx.x & 31;
    int wid  = threadIdx.x >> 5;
    int mstart = blockIdx.y * 32;
    unsigned lt = (1u << lane) - 1u;

    for (int m = mstart + wid; m < mstart + 32; m += 8) {
        int ci = samp[b*MM + m];
        float cx = sx[ci], cy = sy[ci], cz = sz[ci];
        int cnt0 = 0, cnt1 = 0, f0 = -1, f1 = -1;
        int* out0 = gidx0 + ((size_t)(b*MM + m))*K0;
        int* out1 = gidx1 + ((size_t)(b*MM + m))*K1;

        for (int base = 0; base < NN && (cnt0 < K0 || cnt1 < K1); base += 32) {
            int i = base + lane;
            float dx = sx[i] - cx;
            float dy = sy[i] - cy;
            float dz = sz[i] - cz;
            float d = __fadd_rn(__fadd_rn(__fmul_rn(dx,dx), __fmul_rn(dy,dy)), __fmul_rn(dz,dz));
            bool ok0 = d < r2a;
            bool ok1 = d < r2b;
            unsigned m0 = __ballot_sync(0xffffffffu, ok0);
            unsigned m1 = __ballot_sync(0xffffffffu, ok1);
            if (f0 < 0 && m0) f0 = base + __ffs(m0) - 1;
            if (f1 < 0 && m1) f1 = base + __ffs(m1) - 1;
            int p0 = cnt0 + __popc(m0 & lt);
            int p1 = cnt1 + __popc(m1 & lt);
            if (ok0 && p0 < K0) out0[p0] = i;
            if (ok1 && p1 < K1) out1[p1] = i;
            cnt0 = min(K0, cnt0 + __popc(m0));
            cnt1 = min(K1, cnt1 + __popc(m1));
        }
        for (int p = cnt0 + lane; p < K0; p += 32) out0[p] = f0;
        for (int p = cnt1 + lane; p < K1; p += 32) out1[p] = f1;
    }
}

// ---------------- Tiled GEMM: 64 out x 256 pos per block, FFMA2, 8x8 thread tile ----------------
template<bool GATHER, bool POOL>
__global__ __launch_bounds__(256, 2) void conv_kernel(
    const float* __restrict__ xin, const float* __restrict__ Wt,
    const float* __restrict__ bias,
    const float* __restrict__ bns, const float* __restrict__ bnt,
    float* __restrict__ y, float* __restrict__ ps, float* __restrict__ ps2,
    float* __restrict__ pmax, float* __restrict__ pmin,
    int cin, int nk, int cout, int copad, int P, int K,
    const float* __restrict__ pc, const float* __restrict__ ft,
    const float* __restrict__ newpc, const int* __restrict__ gidx,
    int mkshift, int kshift)
{
    __shared__ __align__(16) float xs[2][16][256];
    __shared__ __align__(16) float ws[2][16][64];
    __shared__ float ssA[96], stA[96];
    __shared__ int sidx[256];

    const int tx = threadIdx.x, ty = threadIdx.y;
    const int t  = ty*32 + tx;
    const int pblock = blockIdx.x * 256;
    const int oblock = blockIdx.y * 64;
    const int nblk = gridDim.x;

    if (GATHER) {
        sidx[t] = gidx[pblock + t];
    } else {
        if (t < cin) { ssA[t] = bns[t]; stA[t] = bnt[t]; }
    }
    __syncthreads();

    int g_bb = 0, g_mm = 0, g_ix = 0;
    size_t g_fb = 0;
    if (GATHER) {
        int p = pblock + t;
        g_bb = p >> mkshift;
        g_mm = (p >> kshift) & (MM - 1);
        g_ix = sidx[t];
        g_fb = ((size_t)g_bb*NN + g_ix)*64;
    }

    float4 xr[4];
    float  gxr[16];
    float4 wr = make_float4(0,0,0,0);
    const int wcc = t >> 4, wo4 = t & 15;

    auto load_x = [&](int kc) {
        if (GATHER) {
            if (kc < 4) {
#pragma unroll
                for (int j = 0; j < 4; j++) {
                    float4 v = *(const float4*)&ft[g_fb + kc*16 + j*4];
                    gxr[j*4+0] = v.x; gxr[j*4+1] = v.y; gxr[j*4+2] = v.z; gxr[j*4+3] = v.w;
                }
            } else {
#pragma unroll
                for (int i = 0; i < 16; i++) gxr[i] = 0.0f;
#pragma unroll
                for (int d = 0; d < 3; d++)
                    gxr[d] = pc[(size_t)(g_bb*3 + d)*NN + g_ix] - newpc[(size_t)(g_bb*3 + d)*MM + g_mm];
            }
        } else {
            int c0 = kc * 16;
#pragma unroll
            for (int i = 0; i < 4; i++) {
                int f  = t + i*256;
                int cc = f >> 6, q = f & 63;
                int c  = c0 + cc;
                float4 v = *(const float4*)&xin[(size_t)c*P + pblock + q*4];
                float sc = ssA[c], tc = stA[c];
                v.x = fmaxf(v.x*sc + tc, 0.0f);
                v.y = fmaxf(v.y*sc + tc, 0.0f);
                v.z = fmaxf(v.z*sc + tc, 0.0f);
                v.w = fmaxf(v.w*sc + tc, 0.0f);
                xr[i] = v;
            }
        }
    };
    auto load_w = [&](int kc) {
        wr = *(const float4*)&Wt[(size_t)(kc*16 + wcc)*copad + oblock + wo4*4];
    };
    auto store_stage = [&](int buf) {
        if (GATHER) {
#pragma unroll
            for (int i = 0; i < 16; i++) xs[buf][i][t] = gxr[i];
        } else {
#pragma unroll
            for (int i = 0; i < 4; i++) {
                int f  = t + i*256;
                int cc = f >> 6, q = f & 63;
                *(float4*)&xs[buf][cc][q*4] = xr[i];
            }
        }
        *(float4*)&ws[buf][wcc][wo4*4] = wr;
    };

    unsigned long long acc[8][4];
#pragma unroll
    for (int o = 0; o < 8; o++)
#pragma unroll
        for (int p = 0; p < 4; p++) acc[o][p] = 0ULL;

    load_x(0); load_w(0); store_stage(0);
    __syncthreads();

    for (int kc = 0; kc < nk; kc++) {
        int buf = kc & 1;
        if (kc + 1 < nk) { load_x(kc + 1); load_w(kc + 1); }
#pragma unroll
        for (int cc = 0; cc < 16; cc++) {
            float4 w0 = *(const float4*)&ws[buf][cc][ty*8];
            float4 w1 = *(const float4*)&ws[buf][cc][ty*8 + 4];
            ulonglong2 a01 = *(const ulonglong2*)&xs[buf][cc][tx*4];
            ulonglong2 b01 = *(const ulonglong2*)&xs[buf][cc][128 + tx*4];
            unsigned long long wp0, wp1, wp2, wp3, wp4, wp5, wp6, wp7;
            PACK2(wp0, w0.x); PACK2(wp1, w0.y); PACK2(wp2, w0.z); PACK2(wp3, w0.w);
            PACK2(wp4, w1.x); PACK2(wp5, w1.y); PACK2(wp6, w1.z); PACK2(wp7, w1.w);
            FMA2(acc[0][0], a01.x, wp0); FMA2(acc[0][1], a01.y, wp0);
            FMA2(acc[0][2], b01.x, wp0); FMA2(acc[0][3], b01.y, wp0);
            FMA2(acc[1][0], a01.x, wp1); FMA2(acc[1][1], a01.y, wp1);
            FMA2(acc[1][2], b01.x, wp1); FMA2(acc[1][3], b01.y, wp1);
            FMA2(acc[2][0], a01.x, wp2); FMA2(acc[2][1], a01.y, wp2);
            FMA2(acc[2][2], b01.x, wp2); FMA2(acc[2][3], b01.y, wp2);
            FMA2(acc[3][0], a01.x, wp3); FMA2(acc[3][1], a01.y, wp3);
            FMA2(acc[3][2], b01.x, wp3); FMA2(acc[3][3], b01.y, wp3);
            FMA2(acc[4][0], a01.x, wp4); FMA2(acc[4][1], a01.y, wp4);
            FMA2(acc[4][2], b01.x, wp4); FMA2(acc[4][3], b01.y, wp4);
            FMA2(acc[5][0], a01.x, wp5); FMA2(acc[5][1], a01.y, wp5);
            FMA2(acc[5][2], b01.x, wp5); FMA2(acc[5][3], b01.y, wp5);
            FMA2(acc[6][0], a01.x, wp6); FMA2(acc[6][1], a01.y, wp6);
            FMA2(acc[6][2], b01.x, wp6); FMA2(acc[6][3], b01.y, wp6);
            FMA2(acc[7][0], a01.x, wp7); FMA2(acc[7][1], a01.y, wp7);
            FMA2(acc[7][2], b01.x, wp7); FMA2(acc[7][3], b01.y, wp7);
        }
        if (kc + 1 < nk) store_stage(buf ^ 1);
        __syncthreads();
    }

    int pbase0 = pblock + tx*4;
#pragma unroll
    for (int o = 0; o < 8; o++) {
        int oc = oblock + ty*8 + o;
        bool valid = (oc < cout);
        float bv = valid ? bias[oc] : 0.0f;
        float2 u0 = unpk(acc[o][0]);
        float2 u1 = unpk(acc[o][1]);
        float2 u2 = unpk(acc[o][2]);
        float2 u3 = unpk(acc[o][3]);
        float4 r0 = make_float4(u0.x+bv, u0.y+bv, u1.x+bv, u1.y+bv);
        float4 r1 = make_float4(u2.x+bv, u2.y+bv, u3.x+bv, u3.y+bv);
        if (!POOL && valid) {
            *(float4*)&y[(size_t)oc*P + pbase0]       = r0;
            *(float4*)&y[(size_t)oc*P + pbase0 + 128] = r1;
        }
        float s1 = ((r0.x+r0.y)+(r0.z+r0.w)) + ((r1.x+r1.y)+(r1.z+r1.w));
        float s2 = (r0.x*r0.x + r0.y*r0.y + r0.z*r0.z + r0.w*r0.w)
                 + (r1.x*r1.x + r1.y*r1.y + r1.z*r1.z + r1.w*r1.w);
#pragma unroll
        for (int off = 16; off > 0; off >>= 1) {
            s1 += __shfl_down_sync(0xffffffffu, s1, off);
            s2 += __shfl_down_sync(0xffffffffu, s2, off);
        }
        if (tx == 0 && valid) {
            ps [(size_t)oc*nblk + blockIdx.x] = s1;
            ps2[(size_t)oc*nblk + blockIdx.x] = s2;
        }
        if (POOL) {
            float mxA = fmaxf(fmaxf(r0.x, r0.y), fmaxf(r0.z, r0.w));
            float mnA = fminf(fminf(r0.x, r0.y), fminf(r0.z, r0.w));
            float mxB = fmaxf(fmaxf(r1.x, r1.y), fmaxf(r1.z, r1.w));
            float mnB = fminf(fminf(r1.x, r1.y), fminf(r1.z, r1.w));
            if (K == 32) {
#pragma unroll
                for (int off = 4; off > 0; off >>= 1) {
                    mxA = fmaxf(mxA, __shfl_xor_sync(0xffffffffu, mxA, off));
                    mnA = fminf(mnA, __shfl_xor_sync(0xffffffffu, mnA, off));
                    mxB = fmaxf(mxB, __shfl_xor_sync(0xffffffffu, mxB, off));
                    mnB = fminf(mnB, __shfl_xor_sync(0xffffffffu, mnB, off));
                }
                if ((tx & 7) == 0 && valid) {
                    int gA = (pblock >> 5) + (tx >> 3);
                    int gB = gA + 4;
                    pmax[(size_t)oc*GCOUNT + gA] = mxA;
                    pmin[(size_t)oc*GCOUNT + gA] = mnA;
                    pmax[(size_t)oc*GCOUNT + gB] = mxB;
                    pmin[(size_t)oc*GCOUNT + gB] = mnB;
                }
            } else { // K == 64
#pragma unroll
                for (int off = 8; off > 0; off >>= 1) {
                    mxA = fmaxf(mxA, __shfl_xor_sync(0xffffffffu, mxA, off));
                    mnA = fminf(mnA, __shfl_xor_sync(0xffffffffu, mnA, off));
                    mxB = fmaxf(mxB, __shfl_xor_sync(0xffffffffu, mxB, off));
                    mnB = fminf(mnB, __shfl_xor_sync(0xffffffffu, mnB, off));
                }
                if ((tx & 15) == 0 && valid) {
                    int gA = (pblock >> 6) + (tx >> 4);
                    int gB = gA + 2;
                    pmax[(size_t)oc*GCOUNT + gA] = mxA;
                    pmin[(size_t)oc*GCOUNT + gA] = mnA;
                    pmax[(size_t)oc*GCOUNT + gB] = mxB;
                    pmin[(size_t)oc*GCOUNT + gB] = mnB;
                }
            }
        }
    }
}

// ---------------- finalize BN: reduce partials -> (scale, shift) ----------------
__global__ __launch_bounds__(256) void finalize_kernel(const float* __restrict__ ps,
                                                       const float* __restrict__ ps2,
                                                       int nblk, float invP,
                                                       const float* __restrict__ gamma,
                                                       const float* __restrict__ beta,
                                                       float* __restrict__ s,
                                                       float* __restrict__ t)
{
    int c = blockIdx.x;
    float a = 0.0f, b = 0.0f;
    for (int i = threadIdx.x; i < nblk; i += 256) {
        a += ps [(size_t)c*nblk + i];
        b += ps2[(size_t)c*nblk + i];
    }
#pragma unroll
    for (int off = 16; off > 0; off >>= 1) {
        a += __shfl_down_sync(0xffffffffu, a, off);
        b += __shfl_down_sync(0xffffffffu, b, off);
    }
    __shared__ float sa[8], sb[8];
    int lane = threadIdx.x & 31, w = threadIdx.x >> 5;
    if (lane == 0) { sa[w] = a; sb[w] = b; }
    __syncthreads();
    if (threadIdx.x < 8) {
        a = sa[threadIdx.x]; b = sb[threadIdx.x];
#pragma unroll
        for (int off = 4; off > 0; off >>= 1) {
            a += __shfl_down_sync(0xffu, a, off);
            b += __shfl_down_sync(0xffu, b, off);
        }
        if (threadIdx.x == 0) {
            float mu  = a * invP;
            float var = b * invP - mu*mu;
            float rs  = 1.0f / sqrtf(var + 1e-5f);
            float sc  = gamma[c] * rs;
            s[c] = sc;
            t[c] = beta[c] - mu * sc;
        }
    }
}

// ---------------- apply BN to pooled max/min, write output ----------------
__global__ __launch_bounds__(256) void pool_apply_kernel(const float* __restrict__ pmax,
                                                         const float* __restrict__ pmin,
                                                         const float* __restrict__ s,
                                                         const float* __restrict__ t,
                                                         float* __restrict__ out,
                                                         int chbase)
{
    int gid = blockIdx.x*256 + threadIdx.x;
    int oc = gid >> 14;
    int g  = gid & 16383;
    float sc = s[oc], tc = t[oc];
    float v  = (sc > 0.0f) ? pmax[gid] : pmin[gid];
    float r  = fmaxf(v*sc + tc, 0.0f);
    int b = g >> 10, m = g & 1023;
    out[OUT_OFS + ((size_t)(b*256 + chbase + oc))*MM + m] = r;
}

// ---------------- host launch sequence ----------------
extern "C" void kernel_launch(void* const* d_in, const int* in_sizes, int n_in,
                              void* d_out, int out_size)
{
    const float* pc   = (const float*)d_in[0];
    const float* feat = (const float*)d_in[1];
    const float *Wp[6], *bp[6], *gp[6], *bep[6];
    for (int i = 0; i < 6; i++) {
        Wp[i]  = (const float*)d_in[2 + 4*i];
        bp[i]  = (const float*)d_in[3 + 4*i];
        gp[i]  = (const float*)d_in[4 + 4*i];
        bep[i] = (const float*)d_in[5 + 4*i];
    }
    float* out = (float*)d_out;

    int *samp, *idx0, *idx1;
    float *bufA, *bufB, *ft, *sv, *tv, *ps, *ps2, *pmax, *pmin, *wt;
    cudaGetSymbolAddress((void**)&samp, g_samp);
    cudaGetSymbolAddress((void**)&idx0, g_idx0);
    cudaGetSymbolAddress((void**)&idx1, g_idx1);
    cudaGetSymbolAddress((void**)&bufA, g_bufA);
    cudaGetSymbolAddress((void**)&bufB, g_bufB);
    cudaGetSymbolAddress((void**)&ft,   g_ft);
    cudaGetSymbolAddress((void**)&sv,   g_s);
    cudaGetSymbolAddress((void**)&tv,   g_t);
    cudaGetSymbolAddress((void**)&ps,   g_ps);
    cudaGetSymbolAddress((void**)&ps2,  g_ps2);
    cudaGetSymbolAddress((void**)&pmax, g_pmax);
    cudaGetSymbolAddress((void**)&pmin, g_pmin);
    cudaGetSymbolAddress((void**)&wt,   g_wt);

    const float r2_0 = (float)(0.1*0.1);
    const float r2_1 = (float)(0.2*0.2);

    WPtrs wargs;
    for (int l = 0; l < 6; l++) wargs.w[l] = Wp[l];
    wtr_kernel<<<6, 256>>>(wargs, wt);
    ftr_kernel<<<dim3(128, 2, BB), dim3(32, 8)>>>(feat, ft);
    fps_kernel<<<BB, 512>>>(pc, samp, out);
    ballquery2_kernel<<<dim3(BB,32), 256, 3*NN*sizeof(float)>>>(pc, samp, idx0, idx1, r2_0, r2_1);

    dim3 tb(32, 8);
    const int nbx0 = P0/256, nbx1 = P1/256;

    // -------- branch 0 (K=32): 67 -> 64 -> 64 -> 128 --------
    conv_kernel<true,false><<<dim3(nbx0, 1), tb>>>(nullptr, wt + 0*12288, bp[0], nullptr, nullptr,
        bufA, ps, ps2, nullptr, nullptr, 67, 5, 64, 64, P0, K0, pc, ft, out, idx0, 15, 5);
    finalize_kernel<<<64, 256>>>(ps, ps2, nbx0, 1.0f/(float)P0, gp[0], bep[0], sv, tv);
    conv_kernel<false,false><<<dim3(nbx0, 1), tb>>>(bufA, wt + 1*12288, bp[1], sv, tv,
        bufB, ps, ps2, nullptr, nullptr, 64, 4, 64, 64, P0, K0, nullptr, nullptr, nullptr, nullptr, 0, 0);
    finalize_kernel<<<64, 256>>>(ps, ps2, nbx0, 1.0f/(float)P0, gp[1], bep[1], sv, tv);
    conv_kernel<false,true><<<dim3(nbx0, 2), tb>>>(bufB, wt + 2*12288, bp[2], sv, tv,
        nullptr, ps, ps2, pmax, pmin, 64, 4, 128, 128, P0, K0, nullptr, nullptr, nullptr, nullptr, 0, 0);
    finalize_kernel<<<128, 256>>>(ps, ps2, nbx0, 1.0f/(float)P0, gp[2], bep[2], sv, tv);
    pool_apply_kernel<<<(128*GCOUNT)/256, 256>>>(pmax, pmin, sv, tv, out, 0);

    // -------- branch 1 (K=64): 67 -> 64 -> 96 -> 128 --------
    conv_kernel<true,false><<<dim3(nbx1, 1), tb>>>(nullptr, wt + 3*12288, bp[3], nullptr, nullptr,
        bufA, ps, ps2, nullptr, nullptr, 67, 5, 64, 64, P1, K1, pc, ft, out, idx1, 16, 6);
    finalize_kernel<<<64, 256>>>(ps, ps2, nbx1, 1.0f/(float)P1, gp[3], bep[3], sv, tv);
    conv_kernel<false,false><<<dim3(nbx1, 2), tb>>>(bufA, wt + 4*12288, bp[4], sv, tv,
        bufB, ps, ps2, nullptr, nullptr, 64, 4, 96, 128, P1, K1, nullptr, nullptr, nullptr, nullptr, 0, 0);
    finalize_kernel<<<96, 256>>>(ps, ps2, nbx1, 1.0f/(float)P1, gp[4], bep[4], sv, tv);
    conv_kernel<false,true><<<dim3(nbx1, 2), tb>>>(bufB, wt + 5*12288, bp[5], sv, tv,
        nullptr, ps, ps2, pmax, pmin, 96, 6, 128, 128, P1, K1, nullptr, nullptr, nullptr, nullptr, 0, 0);
    finalize_kernel<<<128, 256>>>(ps, ps2, nbx1, 1.0f/(float)P1, gp[5], bep[5], sv, tv);
    pool_apply_kernel<<<(128*GCOUNT)/256, 256>>>(pmax, pmin, sv, tv, out, 128);
}